// round 5
// baseline (speedup 1.0000x reference)
#include <cuda_runtime.h>
#include <cuda_fp16.h>
#include <math.h>
#include <stdint.h>

#define N_NODES 50000
#define E_EDGES 800000
#define HID 256
#define NCLASS 10
#define NGRAPH 512

// ---------------- device scratch (static; no cudaMalloc allowed) --------------
__device__ float  g_h[(size_t)N_NODES * HID];     // 51.2 MB fp32
__device__ __half g_h2h[(size_t)N_NODES * HID];   // 25.6 MB fp16 (pre-agg)
__device__ float  g_Wt[3 * HID * HID];            // tf32-rounded weights [K][N]
__device__ float  g_dinv[N_NODES];
__device__ int    g_deg[N_NODES];
__device__ int    g_indptr[N_NODES + 1];
__device__ int    g_cursor[N_NODES];
__device__ int    g_csrsrc[E_EDGES + N_NODES];
__device__ int    g_gstart[NGRAPH + 1];
__device__ int    g_part[64];

// ---------------- helpers -----------------------------------------------------
__device__ __forceinline__ uint32_t smem_u32(const void* p) {
    uint32_t a;
    asm("{ .reg .u64 t; cvta.to.shared.u64 t, %1; cvt.u32.u64 %0, t; }" : "=r"(a) : "l"(p));
    return a;
}
__device__ __forceinline__ uint32_t f2tf32(float f) {
    uint32_t o;
    asm("cvt.rna.tf32.f32 %0, %1;" : "=r"(o) : "f"(f));
    return o;
}
__device__ __forceinline__ void mma_tf32(float* d, const uint32_t* a, const uint32_t* b) {
    asm volatile(
        "mma.sync.aligned.m16n8k8.row.col.f32.tf32.tf32.f32 "
        "{%0,%1,%2,%3}, {%4,%5,%6,%7}, {%8,%9}, {%0,%1,%2,%3};"
        : "+f"(d[0]), "+f"(d[1]), "+f"(d[2]), "+f"(d[3])
        : "r"(a[0]), "r"(a[1]), "r"(a[2]), "r"(a[3]), "r"(b[0]), "r"(b[1]));
}
#define CP_ASYNC16(dst, src, sz) \
    asm volatile("cp.async.cg.shared.global [%0], [%1], 16, %2;" :: "r"(dst), "l"(src), "r"(sz))
#define CP_COMMIT()   asm volatile("cp.async.commit_group;" ::: "memory")
#define CP_WAIT(n)    asm volatile("cp.async.wait_group %0;" :: "n"(n) : "memory")

// ---------------- fused setup: zero deg + tf32 weights + graph starts ---------
__global__ void k_setup(const float* __restrict__ enc_W, const float* __restrict__ conv_W,
                        const int* __restrict__ batch) {
    int id = blockIdx.x * blockDim.x + threadIdx.x;
    if (id < N_NODES) g_deg[id] = 0;
    if (id < 3 * HID * HID) {
        int w = id / (HID * HID);
        int off = id - w * HID * HID;
        float v = (w == 0) ? enc_W[off] : conv_W[(w - 1) * HID * HID + off];
        ((uint32_t*)g_Wt)[id] = f2tf32(v);
    }
    if (id <= NGRAPH) {
        int lo = 0, hi = N_NODES;
        while (lo < hi) {
            int mid = (lo + hi) >> 1;
            if (batch[mid] < id) lo = mid + 1; else hi = mid;
        }
        g_gstart[id] = lo;
    }
}

__global__ void k_count_deg(const int* __restrict__ col) {
    int stride = gridDim.x * blockDim.x;
    for (int e = blockIdx.x * blockDim.x + threadIdx.x; e < E_EDGES; e += stride)
        atomicAdd(&g_deg[col[e]], 1);
}

// local scan over d = deg+1, also produces dinv
__global__ void k_scan_local() {
    __shared__ int s[1024];
    int tid = threadIdx.x;
    int i = blockIdx.x * 1024 + tid;
    int v = 0;
    if (i < N_NODES) {
        int d = g_deg[i] + 1;
        v = d;
        g_dinv[i] = rsqrtf((float)d);
    }
    s[tid] = v;
    __syncthreads();
    for (int off = 1; off < 1024; off <<= 1) {
        int t = (tid >= off) ? s[tid - off] : 0;
        __syncthreads();
        s[tid] += t;
        __syncthreads();
    }
    if (i < N_NODES) g_indptr[i] = s[tid] - v;
    if (tid == 1023) g_part[blockIdx.x] = s[1023];
}
__global__ void k_scan_part() {
    __shared__ int s[64];
    int t = threadIdx.x;
    int nb = (N_NODES + 1023) / 1024;
    int v = (t < nb) ? g_part[t] : 0;
    s[t] = v;
    __syncthreads();
    for (int off = 1; off < 64; off <<= 1) {
        int x = (t >= off) ? s[t - off] : 0;
        __syncthreads();
        s[t] += x;
        __syncthreads();
    }
    g_part[t] = s[t] - v;
}
__global__ void k_scan_add() {
    int i = blockIdx.x * 1024 + threadIdx.x;
    if (i < N_NODES) {
        int v = g_indptr[i] + g_part[blockIdx.x];
        g_indptr[i] = v;
        g_cursor[i] = v;
    }
    if (i == 0) g_indptr[N_NODES] = E_EDGES + N_NODES;
}
__global__ void k_fill_csr(const int* __restrict__ row, const int* __restrict__ col) {
    int stride = gridDim.x * blockDim.x;
    for (int t = blockIdx.x * blockDim.x + threadIdx.x; t < E_EDGES + N_NODES; t += stride) {
        int v, srcv;
        if (t < E_EDGES) { v = col[t]; srcv = row[t]; }
        else             { v = t - E_EDGES; srcv = v; }
        int p = atomicAdd(&g_cursor[v], 1);
        g_csrsrc[p] = srcv;
    }
}

// ---------------- tf32 mma.sync GEMM: [M,256] @ [256,256] --------------------
// Block 128x128, 8 warps (4x2), warp tile 32x64, K chunks of 32, cp.async DB.
// Output: fp32 C (+bias) when Ch==nullptr, else fp16 Ch (no bias).
#define A_PITCH 36
#define B_PITCH 136
#define A_TILE_B (128 * A_PITCH * 4)
#define B_TILE_B (32 * B_PITCH * 4)
#define BUF_B    (A_TILE_B + B_TILE_B)
#define GEMM_SMEM (2 * BUF_B)

__global__ void __launch_bounds__(256, 2)
k_gemm_tc(const float* __restrict__ A, const float* __restrict__ W,
          const float* __restrict__ bias, float* __restrict__ C,
          __half* __restrict__ Ch, int M) {
    extern __shared__ char smem[];
    uint32_t sb = smem_u32(smem);
    int tid = threadIdx.x;
    int lane = tid & 31, wid = tid >> 5;
    int warp_m = wid & 3, warp_n = wid >> 2;
    int g = lane >> 2, tig = lane & 3;
    int bm = blockIdx.x * 128;
    int bn = blockIdx.y * 128;

    float acc[2][8][4];
#pragma unroll
    for (int mt = 0; mt < 2; mt++)
#pragma unroll
        for (int nt = 0; nt < 8; nt++)
#pragma unroll
            for (int j = 0; j < 4; j++) acc[mt][nt][j] = 0.f;

    auto load_chunk = [&](int c, int buf) {
        int k0 = c * 32;
        uint32_t abase = sb + buf * BUF_B;
        uint32_t bbase = abase + A_TILE_B;
#pragma unroll
        for (int i = 0; i < 4; i++) {
            int f = tid + i * 256;
            int row = f >> 3, c4 = f & 7;
            int gr = bm + row;
            const float* src = A + (size_t)gr * HID + k0 + c4 * 4;
            uint32_t dst = abase + (row * A_PITCH + c4 * 4) * 4;
            uint32_t sz = (gr < M) ? 16u : 0u;
            CP_ASYNC16(dst, src, sz);
        }
#pragma unroll
        for (int i = 0; i < 4; i++) {
            int f = tid + i * 256;
            int row = f >> 5, c4 = f & 31;
            const float* src = W + (size_t)(k0 + row) * HID + bn + c4 * 4;
            uint32_t dst = bbase + (row * B_PITCH + c4 * 4) * 4;
            CP_ASYNC16(dst, src, 16u);
        }
        CP_COMMIT();
    };

    load_chunk(0, 0);

    for (int c = 0; c < 8; c++) {
        int buf = c & 1;
        if (c < 7) {
            load_chunk(c + 1, buf ^ 1);
            CP_WAIT(1);
        } else {
            CP_WAIT(0);
        }
        __syncthreads();

        const uint32_t* As = (const uint32_t*)(smem + buf * BUF_B);
        const uint32_t* Bs = (const uint32_t*)(smem + buf * BUF_B + A_TILE_B);

#pragma unroll
        for (int ks = 0; ks < 4; ks++) {
            int kl = ks * 8;
            uint32_t afr[2][4];
#pragma unroll
            for (int mt = 0; mt < 2; mt++) {
                int m0 = warp_m * 32 + mt * 16;
                afr[mt][0] = As[(m0 + g) * A_PITCH + kl + tig];
                afr[mt][1] = As[(m0 + 8 + g) * A_PITCH + kl + tig];
                afr[mt][2] = As[(m0 + g) * A_PITCH + kl + tig + 4];
                afr[mt][3] = As[(m0 + 8 + g) * A_PITCH + kl + tig + 4];
            }
            uint32_t bfr[8][2];
#pragma unroll
            for (int nt = 0; nt < 8; nt++) {
                int n0 = warp_n * 64 + nt * 8;
                bfr[nt][0] = Bs[(kl + tig) * B_PITCH + n0 + g];
                bfr[nt][1] = Bs[(kl + tig + 4) * B_PITCH + n0 + g];
            }
#pragma unroll
            for (int mt = 0; mt < 2; mt++)
#pragma unroll
                for (int nt = 0; nt < 8; nt++)
                    mma_tf32(acc[mt][nt], afr[mt], bfr[nt]);
        }
        __syncthreads();
    }

    // epilogue
#pragma unroll
    for (int mt = 0; mt < 2; mt++) {
        int m_base = bm + warp_m * 32 + mt * 16;
        int row0 = m_base + g;
        int row1 = m_base + 8 + g;
#pragma unroll
        for (int nt = 0; nt < 8; nt++) {
            int n = bn + warp_n * 64 + nt * 8 + 2 * tig;
            if (Ch) {
                if (row0 < M)
                    *(__half2*)&Ch[(size_t)row0 * HID + n] =
                        __floats2half2_rn(acc[mt][nt][0], acc[mt][nt][1]);
                if (row1 < M)
                    *(__half2*)&Ch[(size_t)row1 * HID + n] =
                        __floats2half2_rn(acc[mt][nt][2], acc[mt][nt][3]);
            } else {
                float2 badd = make_float2(0.f, 0.f);
                if (bias) badd = *(const float2*)&bias[n];
                if (row0 < M) {
                    float2 o = make_float2(acc[mt][nt][0] + badd.x, acc[mt][nt][1] + badd.y);
                    *(float2*)&C[(size_t)row0 * HID + n] = o;
                }
                if (row1 < M) {
                    float2 o = make_float2(acc[mt][nt][2] + badd.x, acc[mt][nt][3] + badd.y);
                    *(float2*)&C[(size_t)row1 * HID + n] = o;
                }
            }
        }
    }
}

// ---------------- pull-based aggregation (fp16 gather, fp32 accumulate) -------
// out[v,f] = relu( dinv[v]*sum_src h2h[src,f]*dinv[src] + b[f] )
// 1 warp per node, 8 halves per lane (16B loads), 8 nodes per 256-block.
__global__ __launch_bounds__(256) void k_aggregate(const __half* __restrict__ h2,
                                                   const float* __restrict__ b,
                                                   float* __restrict__ out) {
    int node = blockIdx.x * 8 + (threadIdx.x >> 5);
    int lane = threadIdx.x & 31;
    int f8 = lane * 8;
    if (node >= N_NODES) return;

    int s = g_indptr[node];
    int e = g_indptr[node + 1];
    float dv = g_dinv[node];

    float acc[8] = {0.f, 0.f, 0.f, 0.f, 0.f, 0.f, 0.f, 0.f};

    int i = s;
    for (; i + 1 < e; i += 2) {
        int s0 = g_csrsrc[i], s1 = g_csrsrc[i + 1];
        float w0 = g_dinv[s0], w1 = g_dinv[s1];
        uint4 p0 = *(const uint4*)&h2[(size_t)s0 * HID + f8];
        uint4 p1 = *(const uint4*)&h2[(size_t)s1 * HID + f8];
        const uint32_t* u0 = &p0.x;
        const uint32_t* u1 = &p1.x;
#pragma unroll
        for (int j = 0; j < 4; j++) {
            float2 a = __half22float2(*(const __half2*)&u0[j]);
            float2 c = __half22float2(*(const __half2*)&u1[j]);
            acc[j * 2 + 0] += a.x * w0 + c.x * w1;
            acc[j * 2 + 1] += a.y * w0 + c.y * w1;
        }
    }
    if (i < e) {
        int s0 = g_csrsrc[i];
        float w0 = g_dinv[s0];
        uint4 p0 = *(const uint4*)&h2[(size_t)s0 * HID + f8];
        const uint32_t* u0 = &p0.x;
#pragma unroll
        for (int j = 0; j < 4; j++) {
            float2 a = __half22float2(*(const __half2*)&u0[j]);
            acc[j * 2 + 0] += a.x * w0;
            acc[j * 2 + 1] += a.y * w0;
        }
    }

    float4 b0 = *(const float4*)&b[f8];
    float4 b1 = *(const float4*)&b[f8 + 4];
    float4 o0, o1;
    o0.x = fmaxf(acc[0] * dv + b0.x, 0.f);
    o0.y = fmaxf(acc[1] * dv + b0.y, 0.f);
    o0.z = fmaxf(acc[2] * dv + b0.z, 0.f);
    o0.w = fmaxf(acc[3] * dv + b0.w, 0.f);
    o1.x = fmaxf(acc[4] * dv + b1.x, 0.f);
    o1.y = fmaxf(acc[5] * dv + b1.y, 0.f);
    o1.z = fmaxf(acc[6] * dv + b1.z, 0.f);
    o1.w = fmaxf(acc[7] * dv + b1.w, 0.f);
    *(float4*)&out[(size_t)node * HID + f8]     = o0;
    *(float4*)&out[(size_t)node * HID + f8 + 4] = o1;
}

// ---------------- fused mean-pool + classifier --------------------------------
__global__ __launch_bounds__(256) void k_pool_cls(const float* __restrict__ h,
                                                  const float* __restrict__ outW,
                                                  const float* __restrict__ outb,
                                                  float* __restrict__ out) {
    int g = blockIdx.x;
    int tid = threadIdx.x;
    __shared__ float sp[HID];

    int s = g_gstart[g];
    int e = g_gstart[g + 1];
    float acc = 0.f;
    for (int n = s; n < e; n++) acc += h[(size_t)n * HID + tid];
    float cnt = (float)(e - s);
    sp[tid] = acc / fmaxf(cnt, 1.0f);
    __syncthreads();

    if (tid < NCLASS) {
        float o = outb[tid];
#pragma unroll 8
        for (int f = 0; f < HID; f++) o += sp[f] * outW[f * NCLASS + tid];
        out[g * NCLASS + tid] = o;
    }
}

// ---------------- launch ------------------------------------------------------
extern "C" void kernel_launch(void* const* d_in, const int* in_sizes, int n_in,
                              void* d_out, int out_size) {
    const float* x      = (const float*)d_in[0];
    const int*   eidx   = (const int*)d_in[1];
    const int*   batch  = (const int*)d_in[2];
    const float* enc_W  = (const float*)d_in[3];
    const float* enc_b  = (const float*)d_in[4];
    const float* conv_W = (const float*)d_in[5];
    const float* conv_b = (const float*)d_in[6];
    const float* out_W  = (const float*)d_in[7];
    const float* out_b  = (const float*)d_in[8];
    float* out = (float*)d_out;

    const int* row = eidx;
    const int* col = eidx + E_EDGES;

    static bool attr_done = false;
    if (!attr_done) {
        cudaFuncSetAttribute(k_gemm_tc, cudaFuncAttributeMaxDynamicSharedMemorySize, GEMM_SMEM);
        attr_done = true;
    }

    int nb = (N_NODES + 1023) / 1024;   // 49

    k_setup<<<(3 * HID * HID + 255) / 256, 256>>>(enc_W, conv_W, batch);
    k_count_deg<<<2048, 256>>>(col);
    k_scan_local<<<nb, 1024>>>();
    k_scan_part<<<1, 64>>>();
    k_scan_add<<<nb, 1024>>>();
    k_fill_csr<<<2048, 256>>>(row, col);

    float*  g_h_ptr;   cudaGetSymbolAddress((void**)&g_h_ptr,   g_h);
    __half* g_h2h_ptr; cudaGetSymbolAddress((void**)&g_h2h_ptr, g_h2h);
    float*  g_Wt_ptr;  cudaGetSymbolAddress((void**)&g_Wt_ptr,  g_Wt);

    dim3 ggrid((N_NODES + 127) / 128, 2);   // 391 x 2

    // encoder (fp32 out + bias)
    k_gemm_tc<<<ggrid, 256, GEMM_SMEM>>>(x, g_Wt_ptr, enc_b, g_h_ptr, nullptr, N_NODES);
    // layer 0: GEMM -> fp16, aggregate -> fp32
    k_gemm_tc<<<ggrid, 256, GEMM_SMEM>>>(g_h_ptr, g_Wt_ptr + HID * HID, nullptr, nullptr, g_h2h_ptr, N_NODES);
    k_aggregate<<<(N_NODES + 7) / 8, 256>>>(g_h2h_ptr, conv_b, g_h_ptr);
    // layer 1
    k_gemm_tc<<<ggrid, 256, GEMM_SMEM>>>(g_h_ptr, g_Wt_ptr + 2 * HID * HID, nullptr, nullptr, g_h2h_ptr, N_NODES);
    k_aggregate<<<(N_NODES + 7) / 8, 256>>>(g_h2h_ptr, conv_b + HID, g_h_ptr);
    // pool + classify
    k_pool_cls<<<NGRAPH, 256>>>(g_h_ptr, out_W, out_b, out);
}

// round 6
// speedup vs baseline: 1.3639x; 1.3639x over previous
#include <cuda_runtime.h>
#include <cuda_fp16.h>
#include <math.h>
#include <stdint.h>

#define N_NODES 50000
#define E_EDGES 800000
#define HID 256
#define NCLASS 10
#define NGRAPH 512

// ---------------- device scratch (static; no cudaMalloc allowed) --------------
__device__ float  g_h[(size_t)N_NODES * HID];     // 51.2 MB fp32
__device__ __half g_h2h[(size_t)N_NODES * HID];   // 25.6 MB fp16 (pre-agg)
__device__ float  g_Wt[3 * HID * HID];            // tf32-rounded weights [K][N]
__device__ float  g_dinv[N_NODES];
__device__ int    g_deg[N_NODES];
__device__ int    g_indptr[N_NODES + 1];
__device__ int    g_cursor[N_NODES];
__device__ int    g_csrsrc[E_EDGES + N_NODES];
__device__ int    g_gstart[NGRAPH + 1];
__device__ int    g_part[64];

// ---------------- helpers -----------------------------------------------------
__device__ __forceinline__ uint32_t smem_u32(const void* p) {
    uint32_t a;
    asm("{ .reg .u64 t; cvta.to.shared.u64 t, %1; cvt.u32.u64 %0, t; }" : "=r"(a) : "l"(p));
    return a;
}
__device__ __forceinline__ uint32_t f2tf32(float f) {
    uint32_t o;
    asm("cvt.rna.tf32.f32 %0, %1;" : "=r"(o) : "f"(f));
    return o;
}
__device__ __forceinline__ void mma_tf32(float* d, const uint32_t* a, const uint32_t* b) {
    asm volatile(
        "mma.sync.aligned.m16n8k8.row.col.f32.tf32.tf32.f32 "
        "{%0,%1,%2,%3}, {%4,%5,%6,%7}, {%8,%9}, {%0,%1,%2,%3};"
        : "+f"(d[0]), "+f"(d[1]), "+f"(d[2]), "+f"(d[3])
        : "r"(a[0]), "r"(a[1]), "r"(a[2]), "r"(a[3]), "r"(b[0]), "r"(b[1]));
}
#define CP_ASYNC16(dst, src, sz) \
    asm volatile("cp.async.cg.shared.global [%0], [%1], 16, %2;" :: "r"(dst), "l"(src), "r"(sz))
#define CP_COMMIT()   asm volatile("cp.async.commit_group;" ::: "memory")
#define CP_WAIT(n)    asm volatile("cp.async.wait_group %0;" :: "n"(n) : "memory")

// ---------------- fused setup: zero deg + tf32 weights + graph starts ---------
__global__ void k_setup(const float* __restrict__ enc_W, const float* __restrict__ conv_W,
                        const int* __restrict__ batch) {
    int id = blockIdx.x * blockDim.x + threadIdx.x;
    if (id < N_NODES) g_deg[id] = 0;
    if (id < 3 * HID * HID) {
        int w = id / (HID * HID);
        int off = id - w * HID * HID;
        float v = (w == 0) ? enc_W[off] : conv_W[(w - 1) * HID * HID + off];
        ((uint32_t*)g_Wt)[id] = f2tf32(v);
    }
    if (id <= NGRAPH) {
        int lo = 0, hi = N_NODES;
        while (lo < hi) {
            int mid = (lo + hi) >> 1;
            if (batch[mid] < id) lo = mid + 1; else hi = mid;
        }
        g_gstart[id] = lo;
    }
}

__global__ void k_count_deg(const int* __restrict__ col) {
    int stride = gridDim.x * blockDim.x;
    for (int e = blockIdx.x * blockDim.x + threadIdx.x; e < E_EDGES; e += stride)
        atomicAdd(&g_deg[col[e]], 1);
}

// local scan over d = deg+1, also produces dinv
__global__ void k_scan_local() {
    __shared__ int s[1024];
    int tid = threadIdx.x;
    int i = blockIdx.x * 1024 + tid;
    int v = 0;
    if (i < N_NODES) {
        int d = g_deg[i] + 1;
        v = d;
        g_dinv[i] = rsqrtf((float)d);
    }
    s[tid] = v;
    __syncthreads();
    for (int off = 1; off < 1024; off <<= 1) {
        int t = (tid >= off) ? s[tid - off] : 0;
        __syncthreads();
        s[tid] += t;
        __syncthreads();
    }
    if (i < N_NODES) g_indptr[i] = s[tid] - v;
    if (tid == 1023) g_part[blockIdx.x] = s[1023];
}
__global__ void k_scan_part() {
    __shared__ int s[64];
    int t = threadIdx.x;
    int nb = (N_NODES + 1023) / 1024;
    int v = (t < nb) ? g_part[t] : 0;
    s[t] = v;
    __syncthreads();
    for (int off = 1; off < 64; off <<= 1) {
        int x = (t >= off) ? s[t - off] : 0;
        __syncthreads();
        s[t] += x;
        __syncthreads();
    }
    g_part[t] = s[t] - v;
}
__global__ void k_scan_add() {
    int i = blockIdx.x * 1024 + threadIdx.x;
    if (i < N_NODES) {
        int v = g_indptr[i] + g_part[blockIdx.x];
        g_indptr[i] = v;
        g_cursor[i] = v;
    }
    if (i == 0) g_indptr[N_NODES] = E_EDGES + N_NODES;
}
__global__ void k_fill_csr(const int* __restrict__ row, const int* __restrict__ col) {
    int stride = gridDim.x * blockDim.x;
    for (int t = blockIdx.x * blockDim.x + threadIdx.x; t < E_EDGES + N_NODES; t += stride) {
        int v, srcv;
        if (t < E_EDGES) { v = col[t]; srcv = row[t]; }
        else             { v = t - E_EDGES; srcv = v; }
        int p = atomicAdd(&g_cursor[v], 1);
        g_csrsrc[p] = srcv;
    }
}

// ---------------- tf32 mma.sync GEMM: [M,256] @ [256,256] --------------------
// Block 128x128, 8 warps (4x2), warp tile 32x64, K chunks of 32, cp.async DB.
// Output: fp32 C (+bias) when Ch==nullptr, else fp16 Ch (no bias).
#define A_PITCH 36
#define B_PITCH 136
#define A_TILE_B (128 * A_PITCH * 4)
#define B_TILE_B (32 * B_PITCH * 4)
#define BUF_B    (A_TILE_B + B_TILE_B)
#define GEMM_SMEM (2 * BUF_B)

__global__ void __launch_bounds__(256, 2)
k_gemm_tc(const float* __restrict__ A, const float* __restrict__ W,
          const float* __restrict__ bias, float* __restrict__ C,
          __half* __restrict__ Ch, int M) {
    extern __shared__ char smem[];
    uint32_t sb = smem_u32(smem);
    int tid = threadIdx.x;
    int lane = tid & 31, wid = tid >> 5;
    int warp_m = wid & 3, warp_n = wid >> 2;
    int g = lane >> 2, tig = lane & 3;
    int bm = blockIdx.x * 128;
    int bn = blockIdx.y * 128;

    float acc[2][8][4];
#pragma unroll
    for (int mt = 0; mt < 2; mt++)
#pragma unroll
        for (int nt = 0; nt < 8; nt++)
#pragma unroll
            for (int j = 0; j < 4; j++) acc[mt][nt][j] = 0.f;

    auto load_chunk = [&](int c, int buf) {
        int k0 = c * 32;
        uint32_t abase = sb + buf * BUF_B;
        uint32_t bbase = abase + A_TILE_B;
#pragma unroll
        for (int i = 0; i < 4; i++) {
            int f = tid + i * 256;
            int row = f >> 3, c4 = f & 7;
            int gr = bm + row;
            const float* src = A + (size_t)gr * HID + k0 + c4 * 4;
            uint32_t dst = abase + (row * A_PITCH + c4 * 4) * 4;
            uint32_t sz = (gr < M) ? 16u : 0u;
            CP_ASYNC16(dst, src, sz);
        }
#pragma unroll
        for (int i = 0; i < 4; i++) {
            int f = tid + i * 256;
            int row = f >> 5, c4 = f & 31;
            const float* src = W + (size_t)(k0 + row) * HID + bn + c4 * 4;
            uint32_t dst = bbase + (row * B_PITCH + c4 * 4) * 4;
            CP_ASYNC16(dst, src, 16u);
        }
        CP_COMMIT();
    };

    load_chunk(0, 0);

    for (int c = 0; c < 8; c++) {
        int buf = c & 1;
        if (c < 7) {
            load_chunk(c + 1, buf ^ 1);
            CP_WAIT(1);
        } else {
            CP_WAIT(0);
        }
        __syncthreads();

        const uint32_t* As = (const uint32_t*)(smem + buf * BUF_B);
        const uint32_t* Bs = (const uint32_t*)(smem + buf * BUF_B + A_TILE_B);

#pragma unroll
        for (int ks = 0; ks < 4; ks++) {
            int kl = ks * 8;
            uint32_t afr[2][4];
#pragma unroll
            for (int mt = 0; mt < 2; mt++) {
                int m0 = warp_m * 32 + mt * 16;
                afr[mt][0] = As[(m0 + g) * A_PITCH + kl + tig];
                afr[mt][1] = As[(m0 + 8 + g) * A_PITCH + kl + tig];
                afr[mt][2] = As[(m0 + g) * A_PITCH + kl + tig + 4];
                afr[mt][3] = As[(m0 + 8 + g) * A_PITCH + kl + tig + 4];
            }
            uint32_t bfr[8][2];
#pragma unroll
            for (int nt = 0; nt < 8; nt++) {
                int n0 = warp_n * 64 + nt * 8;
                bfr[nt][0] = Bs[(kl + tig) * B_PITCH + n0 + g];
                bfr[nt][1] = Bs[(kl + tig + 4) * B_PITCH + n0 + g];
            }
#pragma unroll
            for (int mt = 0; mt < 2; mt++)
#pragma unroll
                for (int nt = 0; nt < 8; nt++)
                    mma_tf32(acc[mt][nt], afr[mt], bfr[nt]);
        }
        __syncthreads();
    }

    // epilogue
#pragma unroll
    for (int mt = 0; mt < 2; mt++) {
        int m_base = bm + warp_m * 32 + mt * 16;
        int row0 = m_base + g;
        int row1 = m_base + 8 + g;
#pragma unroll
        for (int nt = 0; nt < 8; nt++) {
            int n = bn + warp_n * 64 + nt * 8 + 2 * tig;
            if (Ch) {
                if (row0 < M)
                    *(__half2*)&Ch[(size_t)row0 * HID + n] =
                        __floats2half2_rn(acc[mt][nt][0], acc[mt][nt][1]);
                if (row1 < M)
                    *(__half2*)&Ch[(size_t)row1 * HID + n] =
                        __floats2half2_rn(acc[mt][nt][2], acc[mt][nt][3]);
            } else {
                float2 badd = make_float2(0.f, 0.f);
                if (bias) badd = *(const float2*)&bias[n];
                if (row0 < M) {
                    float2 o = make_float2(acc[mt][nt][0] + badd.x, acc[mt][nt][1] + badd.y);
                    *(float2*)&C[(size_t)row0 * HID + n] = o;
                }
                if (row1 < M) {
                    float2 o = make_float2(acc[mt][nt][2] + badd.x, acc[mt][nt][3] + badd.y);
                    *(float2*)&C[(size_t)row1 * HID + n] = o;
                }
            }
        }
    }
}

// ---------------- pull-based aggregation (fp16 gather, fp32 accumulate) -------
// R3 structure: 64 threads/node, 4 nodes per 256-block, one 8B load per
// thread per edge (64 x 8B = full 512B fp16 row). 12500 blocks.
__global__ __launch_bounds__(256) void k_aggregate(const __half* __restrict__ h2,
                                                   const float* __restrict__ b,
                                                   float* __restrict__ out) {
    int node = blockIdx.x * 4 + (threadIdx.x >> 6);
    int f4 = (threadIdx.x & 63) * 4;   // 4 halves per thread
    if (node >= N_NODES) return;

    int s = g_indptr[node];
    int e = g_indptr[node + 1];
    float dv = g_dinv[node];

    float4 acc = make_float4(0.f, 0.f, 0.f, 0.f);
    for (int i = s; i < e; i++) {
        int src = g_csrsrc[i];
        float w = g_dinv[src];
        uint2 p = *(const uint2*)&h2[(size_t)src * HID + f4];
        float2 a = __half22float2(*(const __half2*)&p.x);
        float2 c = __half22float2(*(const __half2*)&p.y);
        acc.x += a.x * w;
        acc.y += a.y * w;
        acc.z += c.x * w;
        acc.w += c.y * w;
    }
    float4 bb = *(const float4*)&b[f4];
    float4 o;
    o.x = fmaxf(acc.x * dv + bb.x, 0.f);
    o.y = fmaxf(acc.y * dv + bb.y, 0.f);
    o.z = fmaxf(acc.z * dv + bb.z, 0.f);
    o.w = fmaxf(acc.w * dv + bb.w, 0.f);
    *(float4*)&out[(size_t)node * HID + f4] = o;
}

// ---------------- fused mean-pool + classifier --------------------------------
__global__ __launch_bounds__(256) void k_pool_cls(const float* __restrict__ h,
                                                  const float* __restrict__ outW,
                                                  const float* __restrict__ outb,
                                                  float* __restrict__ out) {
    int g = blockIdx.x;
    int tid = threadIdx.x;
    __shared__ float sp[HID];

    int s = g_gstart[g];
    int e = g_gstart[g + 1];
    float acc = 0.f;
    for (int n = s; n < e; n++) acc += h[(size_t)n * HID + tid];
    float cnt = (float)(e - s);
    sp[tid] = acc / fmaxf(cnt, 1.0f);
    __syncthreads();

    if (tid < NCLASS) {
        float o = outb[tid];
#pragma unroll 8
        for (int f = 0; f < HID; f++) o += sp[f] * outW[f * NCLASS + tid];
        out[g * NCLASS + tid] = o;
    }
}

// ---------------- launch ------------------------------------------------------
extern "C" void kernel_launch(void* const* d_in, const int* in_sizes, int n_in,
                              void* d_out, int out_size) {
    const float* x      = (const float*)d_in[0];
    const int*   eidx   = (const int*)d_in[1];
    const int*   batch  = (const int*)d_in[2];
    const float* enc_W  = (const float*)d_in[3];
    const float* enc_b  = (const float*)d_in[4];
    const float* conv_W = (const float*)d_in[5];
    const float* conv_b = (const float*)d_in[6];
    const float* out_W  = (const float*)d_in[7];
    const float* out_b  = (const float*)d_in[8];
    float* out = (float*)d_out;

    const int* row = eidx;
    const int* col = eidx + E_EDGES;

    static bool attr_done = false;
    if (!attr_done) {
        cudaFuncSetAttribute(k_gemm_tc, cudaFuncAttributeMaxDynamicSharedMemorySize, GEMM_SMEM);
        attr_done = true;
    }

    int nb = (N_NODES + 1023) / 1024;   // 49

    k_setup<<<(3 * HID * HID + 255) / 256, 256>>>(enc_W, conv_W, batch);
    k_count_deg<<<2048, 256>>>(col);
    k_scan_local<<<nb, 1024>>>();
    k_scan_part<<<1, 64>>>();
    k_scan_add<<<nb, 1024>>>();
    k_fill_csr<<<2048, 256>>>(row, col);

    float*  g_h_ptr;   cudaGetSymbolAddress((void**)&g_h_ptr,   g_h);
    __half* g_h2h_ptr; cudaGetSymbolAddress((void**)&g_h2h_ptr, g_h2h);
    float*  g_Wt_ptr;  cudaGetSymbolAddress((void**)&g_Wt_ptr,  g_Wt);

    dim3 ggrid((N_NODES + 127) / 128, 2);   // 391 x 2

    // encoder (fp32 out + bias)
    k_gemm_tc<<<ggrid, 256, GEMM_SMEM>>>(x, g_Wt_ptr, enc_b, g_h_ptr, nullptr, N_NODES);
    // layer 0: GEMM -> fp16, aggregate -> fp32
    k_gemm_tc<<<ggrid, 256, GEMM_SMEM>>>(g_h_ptr, g_Wt_ptr + HID * HID, nullptr, nullptr, g_h2h_ptr, N_NODES);
    k_aggregate<<<(N_NODES + 3) / 4, 256>>>(g_h2h_ptr, conv_b, g_h_ptr);
    // layer 1
    k_gemm_tc<<<ggrid, 256, GEMM_SMEM>>>(g_h_ptr, g_Wt_ptr + 2 * HID * HID, nullptr, nullptr, g_h2h_ptr, N_NODES);
    k_aggregate<<<(N_NODES + 3) / 4, 256>>>(g_h2h_ptr, conv_b + HID, g_h_ptr);
    // pool + classify
    k_pool_cls<<<NGRAPH, 256>>>(g_h_ptr, out_W, out_b, out);
}

// round 7
// speedup vs baseline: 1.4289x; 1.0477x over previous
#include <cuda_runtime.h>
#include <cuda_fp16.h>
#include <math.h>
#include <stdint.h>

#define N_NODES 50000
#define E_EDGES 800000
#define HID 256
#define NCLASS 10
#define NGRAPH 512

// ---------------- device scratch (static; no cudaMalloc allowed) --------------
__device__ float  g_h[(size_t)N_NODES * HID];     // 51.2 MB fp32
__device__ __half g_h2h[(size_t)N_NODES * HID];   // 25.6 MB fp16 (pre-agg)
__device__ float  g_Wt[3 * HID * HID];            // tf32-rounded weights [K][N]
__device__ float  g_dinv[N_NODES];
__device__ int    g_deg[N_NODES];
__device__ int    g_indptr[N_NODES + 1];
__device__ int    g_cursor[N_NODES];
__device__ int    g_csrsrc[E_EDGES + N_NODES];
__device__ int    g_gstart[NGRAPH + 1];
__device__ int    g_part[64];

// ---------------- helpers -----------------------------------------------------
__device__ __forceinline__ uint32_t smem_u32(const void* p) {
    uint32_t a;
    asm("{ .reg .u64 t; cvta.to.shared.u64 t, %1; cvt.u32.u64 %0, t; }" : "=r"(a) : "l"(p));
    return a;
}
__device__ __forceinline__ uint32_t f2tf32(float f) {
    uint32_t o;
    asm("cvt.rna.tf32.f32 %0, %1;" : "=r"(o) : "f"(f));
    return o;
}
__device__ __forceinline__ void mma_tf32(float* d, const uint32_t* a, const uint32_t* b) {
    asm volatile(
        "mma.sync.aligned.m16n8k8.row.col.f32.tf32.tf32.f32 "
        "{%0,%1,%2,%3}, {%4,%5,%6,%7}, {%8,%9}, {%0,%1,%2,%3};"
        : "+f"(d[0]), "+f"(d[1]), "+f"(d[2]), "+f"(d[3])
        : "r"(a[0]), "r"(a[1]), "r"(a[2]), "r"(a[3]), "r"(b[0]), "r"(b[1]));
}
#define CP_ASYNC16(dst, src, sz) \
    asm volatile("cp.async.cg.shared.global [%0], [%1], 16, %2;" :: "r"(dst), "l"(src), "r"(sz))
#define CP_COMMIT()   asm volatile("cp.async.commit_group;" ::: "memory")
#define CP_WAIT(n)    asm volatile("cp.async.wait_group %0;" :: "n"(n) : "memory")

// ---------------- setup A-side: tf32 weights + graph starts -------------------
__global__ void k_setup_w(const float* __restrict__ enc_W, const float* __restrict__ conv_W,
                          const int* __restrict__ batch) {
    int id = blockIdx.x * blockDim.x + threadIdx.x;
    if (id < 3 * HID * HID) {
        int w = id / (HID * HID);
        int off = id - w * HID * HID;
        float v = (w == 0) ? enc_W[off] : conv_W[(w - 1) * HID * HID + off];
        ((uint32_t*)g_Wt)[id] = f2tf32(v);
    }
    if (id <= NGRAPH) {
        int lo = 0, hi = N_NODES;
        while (lo < hi) {
            int mid = (lo + hi) >> 1;
            if (batch[mid] < id) lo = mid + 1; else hi = mid;
        }
        g_gstart[id] = lo;
    }
}

// ---------------- setup B-side: CSR pipeline ----------------------------------
__global__ void k_zero_deg() {
    int i = blockIdx.x * blockDim.x + threadIdx.x;
    if (i < N_NODES) g_deg[i] = 0;
}
__global__ void k_count_deg(const int* __restrict__ col) {
    int stride = gridDim.x * blockDim.x;
    for (int e = blockIdx.x * blockDim.x + threadIdx.x; e < E_EDGES; e += stride)
        atomicAdd(&g_deg[col[e]], 1);
}
__global__ void k_scan_local() {
    __shared__ int s[1024];
    int tid = threadIdx.x;
    int i = blockIdx.x * 1024 + tid;
    int v = 0;
    if (i < N_NODES) {
        int d = g_deg[i] + 1;
        v = d;
        g_dinv[i] = rsqrtf((float)d);
    }
    s[tid] = v;
    __syncthreads();
    for (int off = 1; off < 1024; off <<= 1) {
        int t = (tid >= off) ? s[tid - off] : 0;
        __syncthreads();
        s[tid] += t;
        __syncthreads();
    }
    if (i < N_NODES) g_indptr[i] = s[tid] - v;
    if (tid == 1023) g_part[blockIdx.x] = s[1023];
}
__global__ void k_scan_part() {
    __shared__ int s[64];
    int t = threadIdx.x;
    int nb = (N_NODES + 1023) / 1024;
    int v = (t < nb) ? g_part[t] : 0;
    s[t] = v;
    __syncthreads();
    for (int off = 1; off < 64; off <<= 1) {
        int x = (t >= off) ? s[t - off] : 0;
        __syncthreads();
        s[t] += x;
        __syncthreads();
    }
    g_part[t] = s[t] - v;
}
__global__ void k_scan_add() {
    int i = blockIdx.x * 1024 + threadIdx.x;
    if (i < N_NODES) {
        int v = g_indptr[i] + g_part[blockIdx.x];
        g_indptr[i] = v;
        g_cursor[i] = v;
    }
    if (i == 0) g_indptr[N_NODES] = E_EDGES + N_NODES;
}
__global__ void k_fill_csr(const int* __restrict__ row, const int* __restrict__ col) {
    int stride = gridDim.x * blockDim.x;
    for (int t = blockIdx.x * blockDim.x + threadIdx.x; t < E_EDGES + N_NODES; t += stride) {
        int v, srcv;
        if (t < E_EDGES) { v = col[t]; srcv = row[t]; }
        else             { v = t - E_EDGES; srcv = v; }
        int p = atomicAdd(&g_cursor[v], 1);
        g_csrsrc[p] = srcv;
    }
}

// ---------------- tf32 mma.sync GEMM: [M,256] @ [256,256] --------------------
#define A_PITCH 36
#define B_PITCH 136
#define A_TILE_B (128 * A_PITCH * 4)
#define B_TILE_B (32 * B_PITCH * 4)
#define BUF_B    (A_TILE_B + B_TILE_B)
#define GEMM_SMEM (2 * BUF_B)

__global__ void __launch_bounds__(256, 2)
k_gemm_tc(const float* __restrict__ A, const float* __restrict__ W,
          const float* __restrict__ bias, float* __restrict__ C,
          __half* __restrict__ Ch, int M) {
    extern __shared__ char smem[];
    uint32_t sb = smem_u32(smem);
    int tid = threadIdx.x;
    int lane = tid & 31, wid = tid >> 5;
    int warp_m = wid & 3, warp_n = wid >> 2;
    int g = lane >> 2, tig = lane & 3;
    int bm = blockIdx.x * 128;
    int bn = blockIdx.y * 128;

    float acc[2][8][4];
#pragma unroll
    for (int mt = 0; mt < 2; mt++)
#pragma unroll
        for (int nt = 0; nt < 8; nt++)
#pragma unroll
            for (int j = 0; j < 4; j++) acc[mt][nt][j] = 0.f;

    auto load_chunk = [&](int c, int buf) {
        int k0 = c * 32;
        uint32_t abase = sb + buf * BUF_B;
        uint32_t bbase = abase + A_TILE_B;
#pragma unroll
        for (int i = 0; i < 4; i++) {
            int f = tid + i * 256;
            int row = f >> 3, c4 = f & 7;
            int gr = bm + row;
            const float* src = A + (size_t)gr * HID + k0 + c4 * 4;
            uint32_t dst = abase + (row * A_PITCH + c4 * 4) * 4;
            uint32_t sz = (gr < M) ? 16u : 0u;
            CP_ASYNC16(dst, src, sz);
        }
#pragma unroll
        for (int i = 0; i < 4; i++) {
            int f = tid + i * 256;
            int row = f >> 5, c4 = f & 31;
            const float* src = W + (size_t)(k0 + row) * HID + bn + c4 * 4;
            uint32_t dst = bbase + (row * B_PITCH + c4 * 4) * 4;
            CP_ASYNC16(dst, src, 16u);
        }
        CP_COMMIT();
    };

    load_chunk(0, 0);

    for (int c = 0; c < 8; c++) {
        int buf = c & 1;
        if (c < 7) {
            load_chunk(c + 1, buf ^ 1);
            CP_WAIT(1);
        } else {
            CP_WAIT(0);
        }
        __syncthreads();

        const uint32_t* As = (const uint32_t*)(smem + buf * BUF_B);
        const uint32_t* Bs = (const uint32_t*)(smem + buf * BUF_B + A_TILE_B);

#pragma unroll
        for (int ks = 0; ks < 4; ks++) {
            int kl = ks * 8;
            uint32_t afr[2][4];
#pragma unroll
            for (int mt = 0; mt < 2; mt++) {
                int m0 = warp_m * 32 + mt * 16;
                afr[mt][0] = As[(m0 + g) * A_PITCH + kl + tig];
                afr[mt][1] = As[(m0 + 8 + g) * A_PITCH + kl + tig];
                afr[mt][2] = As[(m0 + g) * A_PITCH + kl + tig + 4];
                afr[mt][3] = As[(m0 + 8 + g) * A_PITCH + kl + tig + 4];
            }
            uint32_t bfr[8][2];
#pragma unroll
            for (int nt = 0; nt < 8; nt++) {
                int n0 = warp_n * 64 + nt * 8;
                bfr[nt][0] = Bs[(kl + tig) * B_PITCH + n0 + g];
                bfr[nt][1] = Bs[(kl + tig + 4) * B_PITCH + n0 + g];
            }
#pragma unroll
            for (int mt = 0; mt < 2; mt++)
#pragma unroll
                for (int nt = 0; nt < 8; nt++)
                    mma_tf32(acc[mt][nt], afr[mt], bfr[nt]);
        }
        __syncthreads();
    }

    // epilogue
#pragma unroll
    for (int mt = 0; mt < 2; mt++) {
        int m_base = bm + warp_m * 32 + mt * 16;
        int row0 = m_base + g;
        int row1 = m_base + 8 + g;
#pragma unroll
        for (int nt = 0; nt < 8; nt++) {
            int n = bn + warp_n * 64 + nt * 8 + 2 * tig;
            if (Ch) {
                if (row0 < M)
                    *(__half2*)&Ch[(size_t)row0 * HID + n] =
                        __floats2half2_rn(acc[mt][nt][0], acc[mt][nt][1]);
                if (row1 < M)
                    *(__half2*)&Ch[(size_t)row1 * HID + n] =
                        __floats2half2_rn(acc[mt][nt][2], acc[mt][nt][3]);
            } else {
                float2 badd = make_float2(0.f, 0.f);
                if (bias) badd = *(const float2*)&bias[n];
                if (row0 < M) {
                    float2 o = make_float2(acc[mt][nt][0] + badd.x, acc[mt][nt][1] + badd.y);
                    *(float2*)&C[(size_t)row0 * HID + n] = o;
                }
                if (row1 < M) {
                    float2 o = make_float2(acc[mt][nt][2] + badd.x, acc[mt][nt][3] + badd.y);
                    *(float2*)&C[(size_t)row1 * HID + n] = o;
                }
            }
        }
    }
}

// ---------------- pull-based aggregation (fp16 gather, fp32 accumulate) -------
// 64 threads/node, 4 nodes per 256-block (12500 blocks), edge loop unrolled x2
// so each thread keeps two independent csrsrc->dinv->row chains in flight.
__global__ __launch_bounds__(256) void k_aggregate(const __half* __restrict__ h2,
                                                   const float* __restrict__ b,
                                                   float* __restrict__ out) {
    int node = blockIdx.x * 4 + (threadIdx.x >> 6);
    int f4 = (threadIdx.x & 63) * 4;   // 4 halves per thread
    if (node >= N_NODES) return;

    int s = g_indptr[node];
    int e = g_indptr[node + 1];
    float dv = g_dinv[node];

    float4 acc = make_float4(0.f, 0.f, 0.f, 0.f);
    int i = s;
    for (; i + 1 < e; i += 2) {
        int s0 = g_csrsrc[i];
        int s1 = g_csrsrc[i + 1];
        float w0 = g_dinv[s0];
        float w1 = g_dinv[s1];
        uint2 p0 = *(const uint2*)&h2[(size_t)s0 * HID + f4];
        uint2 p1 = *(const uint2*)&h2[(size_t)s1 * HID + f4];
        float2 a0 = __half22float2(*(const __half2*)&p0.x);
        float2 c0 = __half22float2(*(const __half2*)&p0.y);
        float2 a1 = __half22float2(*(const __half2*)&p1.x);
        float2 c1 = __half22float2(*(const __half2*)&p1.y);
        acc.x += a0.x * w0 + a1.x * w1;
        acc.y += a0.y * w0 + a1.y * w1;
        acc.z += c0.x * w0 + c1.x * w1;
        acc.w += c0.y * w0 + c1.y * w1;
    }
    if (i < e) {
        int s0 = g_csrsrc[i];
        float w0 = g_dinv[s0];
        uint2 p0 = *(const uint2*)&h2[(size_t)s0 * HID + f4];
        float2 a0 = __half22float2(*(const __half2*)&p0.x);
        float2 c0 = __half22float2(*(const __half2*)&p0.y);
        acc.x += a0.x * w0;
        acc.y += a0.y * w0;
        acc.z += c0.x * w0;
        acc.w += c0.y * w0;
    }
    float4 bb = *(const float4*)&b[f4];
    float4 o;
    o.x = fmaxf(acc.x * dv + bb.x, 0.f);
    o.y = fmaxf(acc.y * dv + bb.y, 0.f);
    o.z = fmaxf(acc.z * dv + bb.z, 0.f);
    o.w = fmaxf(acc.w * dv + bb.w, 0.f);
    *(float4*)&out[(size_t)node * HID + f4] = o;
}

// ---------------- fused mean-pool + classifier --------------------------------
__global__ __launch_bounds__(256) void k_pool_cls(const float* __restrict__ h,
                                                  const float* __restrict__ outW,
                                                  const float* __restrict__ outb,
                                                  float* __restrict__ out) {
    int g = blockIdx.x;
    int tid = threadIdx.x;
    __shared__ float sp[HID];

    int s = g_gstart[g];
    int e = g_gstart[g + 1];
    float acc = 0.f;
    for (int n = s; n < e; n++) acc += h[(size_t)n * HID + tid];
    float cnt = (float)(e - s);
    sp[tid] = acc / fmaxf(cnt, 1.0f);
    __syncthreads();

    if (tid < NCLASS) {
        float o = outb[tid];
#pragma unroll 8
        for (int f = 0; f < HID; f++) o += sp[f] * outW[f * NCLASS + tid];
        out[g * NCLASS + tid] = o;
    }
}

// ---------------- launch ------------------------------------------------------
extern "C" void kernel_launch(void* const* d_in, const int* in_sizes, int n_in,
                              void* d_out, int out_size) {
    const float* x      = (const float*)d_in[0];
    const int*   eidx   = (const int*)d_in[1];
    const int*   batch  = (const int*)d_in[2];
    const float* enc_W  = (const float*)d_in[3];
    const float* enc_b  = (const float*)d_in[4];
    const float* conv_W = (const float*)d_in[5];
    const float* conv_b = (const float*)d_in[6];
    const float* out_W  = (const float*)d_in[7];
    const float* out_b  = (const float*)d_in[8];
    float* out = (float*)d_out;

    const int* row = eidx;
    const int* col = eidx + E_EDGES;

    static cudaStream_t sB = nullptr;
    static cudaEvent_t evFork = nullptr, evCsr = nullptr;
    static bool init_done = false;
    if (!init_done) {
        cudaFuncSetAttribute(k_gemm_tc, cudaFuncAttributeMaxDynamicSharedMemorySize, GEMM_SMEM);
        cudaStreamCreateWithFlags(&sB, cudaStreamNonBlocking);
        cudaEventCreateWithFlags(&evFork, cudaEventDisableTiming);
        cudaEventCreateWithFlags(&evCsr, cudaEventDisableTiming);
        init_done = true;
    }

    float*  g_h_ptr;   cudaGetSymbolAddress((void**)&g_h_ptr,   g_h);
    __half* g_h2h_ptr; cudaGetSymbolAddress((void**)&g_h2h_ptr, g_h2h);
    float*  g_Wt_ptr;  cudaGetSymbolAddress((void**)&g_Wt_ptr,  g_Wt);

    int nb = (N_NODES + 1023) / 1024;   // 49
    dim3 ggrid((N_NODES + 127) / 128, 2);

    // ---- fork: stream B builds CSR while stream 0 runs weight prep + GEMMs ----
    cudaEventRecord(evFork, 0);
    cudaStreamWaitEvent(sB, evFork, 0);

    // stream B: CSR pipeline
    k_zero_deg<<<(N_NODES + 255) / 256, 256, 0, sB>>>();
    k_count_deg<<<2048, 256, 0, sB>>>(col);
    k_scan_local<<<nb, 1024, 0, sB>>>();
    k_scan_part<<<1, 64, 0, sB>>>();
    k_scan_add<<<nb, 1024, 0, sB>>>();
    k_fill_csr<<<2048, 256, 0, sB>>>(row, col);
    cudaEventRecord(evCsr, sB);

    // stream 0: weights + encoder GEMM + layer-0 GEMM
    k_setup_w<<<(3 * HID * HID + 255) / 256, 256>>>(enc_W, conv_W, batch);
    k_gemm_tc<<<ggrid, 256, GEMM_SMEM>>>(x, g_Wt_ptr, enc_b, g_h_ptr, nullptr, N_NODES);
    k_gemm_tc<<<ggrid, 256, GEMM_SMEM>>>(g_h_ptr, g_Wt_ptr + HID * HID, nullptr, nullptr, g_h2h_ptr, N_NODES);

    // join: first aggregation needs the CSR
    cudaStreamWaitEvent(0, evCsr, 0);

    k_aggregate<<<(N_NODES + 3) / 4, 256>>>(g_h2h_ptr, conv_b, g_h_ptr);
    k_gemm_tc<<<ggrid, 256, GEMM_SMEM>>>(g_h_ptr, g_Wt_ptr + 2 * HID * HID, nullptr, nullptr, g_h2h_ptr, N_NODES);
    k_aggregate<<<(N_NODES + 3) / 4, 256>>>(g_h2h_ptr, conv_b + HID, g_h_ptr);
    k_pool_cls<<<NGRAPH, 256>>>(g_h_ptr, out_W, out_b, out);
}

// round 11
// speedup vs baseline: 1.5926x; 1.1146x over previous
#include <cuda_runtime.h>
#include <cuda_fp16.h>
#include <math.h>
#include <stdint.h>

#define N_NODES 50000
#define E_EDGES 800000
#define HID 256
#define NCLASS 10
#define NGRAPH 512

// ---------------- device scratch (static; no cudaMalloc allowed) --------------
__device__ __half g_xh[(size_t)N_NODES * HID];    // 25.6 MB fp16 (x converted)
__device__ __half g_hh[(size_t)N_NODES * HID];    // 25.6 MB fp16 (activations)
__device__ __half g_h2h[(size_t)N_NODES * HID];   // 25.6 MB fp16 (pre-agg)
__device__ __half g_Wt16[3 * HID * HID];          // fp16 weights, transposed [N][K]
__device__ float  g_dinv[N_NODES];
__device__ int    g_deg[N_NODES];
__device__ int    g_indptr[N_NODES + 1];
__device__ int    g_cursor[N_NODES];
__device__ int    g_csrsrc[E_EDGES + N_NODES];
__device__ int    g_gstart[NGRAPH + 1];
__device__ int    g_part[64];

// ---------------- helpers -----------------------------------------------------
__device__ __forceinline__ uint32_t smem_u32(const void* p) {
    uint32_t a;
    asm("{ .reg .u64 t; cvta.to.shared.u64 t, %1; cvt.u32.u64 %0, t; }" : "=r"(a) : "l"(p));
    return a;
}
__device__ __forceinline__ void mma_f16(float* d, const uint32_t* a, const uint32_t* b) {
    asm volatile(
        "mma.sync.aligned.m16n8k16.row.col.f32.f16.f16.f32 "
        "{%0,%1,%2,%3}, {%4,%5,%6,%7}, {%8,%9}, {%0,%1,%2,%3};"
        : "+f"(d[0]), "+f"(d[1]), "+f"(d[2]), "+f"(d[3])
        : "r"(a[0]), "r"(a[1]), "r"(a[2]), "r"(a[3]), "r"(b[0]), "r"(b[1]));
}
#define CP_ASYNC16(dst, src, sz) \
    asm volatile("cp.async.cg.shared.global [%0], [%1], 16, %2;" :: "r"(dst), "l"(src), "r"(sz))
#define CP_COMMIT()   asm volatile("cp.async.commit_group;" ::: "memory")
#define CP_WAIT(n)    asm volatile("cp.async.wait_group %0;" :: "n"(n) : "memory")

// ---------------- setup: fp16 transposed weights + graph starts ---------------
__global__ void k_setup_w(const float* __restrict__ enc_W, const float* __restrict__ conv_W,
                          const int* __restrict__ batch) {
    int id = blockIdx.x * blockDim.x + threadIdx.x;
    if (id < 3 * HID * HID) {
        int w = id / (HID * HID);
        int off = id - w * HID * HID;
        int k = off >> 8, n = off & 255;
        float v = (w == 0) ? enc_W[off] : conv_W[(w - 1) * HID * HID + off];
        g_Wt16[w * HID * HID + n * HID + k] = __float2half_rn(v);
    }
    if (id <= NGRAPH) {
        int lo = 0, hi = N_NODES;
        while (lo < hi) {
            int mid = (lo + hi) >> 1;
            if (batch[mid] < id) lo = mid + 1; else hi = mid;
        }
        g_gstart[id] = lo;
    }
}

// x fp32 -> fp16
__global__ void k_conv_x(const float* __restrict__ x) {
    int id = blockIdx.x * blockDim.x + threadIdx.x;   // one float4 per thread
    if (id >= N_NODES * HID / 4) return;
    float4 v = *(const float4*)&x[(size_t)id * 4];
    uint2 o;
    *(__half2*)&o.x = __floats2half2_rn(v.x, v.y);
    *(__half2*)&o.y = __floats2half2_rn(v.z, v.w);
    *(uint2*)&g_xh[(size_t)id * 4] = o;
}

// ---------------- CSR pipeline (stream B) -------------------------------------
__global__ void k_zero_deg() {
    int i = blockIdx.x * blockDim.x + threadIdx.x;
    if (i < N_NODES) g_deg[i] = 0;
}
__global__ void k_count_deg(const int* __restrict__ col) {
    int stride = gridDim.x * blockDim.x;
    for (int e = blockIdx.x * blockDim.x + threadIdx.x; e < E_EDGES; e += stride)
        atomicAdd(&g_deg[col[e]], 1);
}
__global__ void k_scan_local() {
    __shared__ int s[1024];
    int tid = threadIdx.x;
    int i = blockIdx.x * 1024 + tid;
    int v = 0;
    if (i < N_NODES) {
        int d = g_deg[i] + 1;
        v = d;
        g_dinv[i] = rsqrtf((float)d);
    }
    s[tid] = v;
    __syncthreads();
    for (int off = 1; off < 1024; off <<= 1) {
        int t = (tid >= off) ? s[tid - off] : 0;
        __syncthreads();
        s[tid] += t;
        __syncthreads();
    }
    if (i < N_NODES) g_indptr[i] = s[tid] - v;
    if (tid == 1023) g_part[blockIdx.x] = s[1023];
}
__global__ void k_scan_part() {
    __shared__ int s[64];
    int t = threadIdx.x;
    int nb = (N_NODES + 1023) / 1024;
    int v = (t < nb) ? g_part[t] : 0;
    s[t] = v;
    __syncthreads();
    for (int off = 1; off < 64; off <<= 1) {
        int x = (t >= off) ? s[t - off] : 0;
        __syncthreads();
        s[t] += x;
        __syncthreads();
    }
    g_part[t] = s[t] - v;
}
__global__ void k_scan_add() {
    int i = blockIdx.x * 1024 + threadIdx.x;
    if (i < N_NODES) {
        int v = g_indptr[i] + g_part[blockIdx.x];
        g_indptr[i] = v;
        g_cursor[i] = v;
    }
    if (i == 0) g_indptr[N_NODES] = E_EDGES + N_NODES;
}
__global__ void k_fill_csr(const int* __restrict__ row, const int* __restrict__ col) {
    int stride = gridDim.x * blockDim.x;
    for (int t = blockIdx.x * blockDim.x + threadIdx.x; t < E_EDGES + N_NODES; t += stride) {
        int v, srcv;
        if (t < E_EDGES) { v = col[t]; srcv = row[t]; }
        else             { v = t - E_EDGES; srcv = v; }
        int p = atomicAdd(&g_cursor[v], 1);
        g_csrsrc[p] = srcv;
    }
}

// ---------------- fp16 mma.sync GEMM: [M,256] @ [256,256] ---------------------
// Block 128x128, 8 warps (4x2), warp tile 32x64, K chunks of 32, cp.async DB.
// A: fp16 [M][256] row-major. W: fp16 [N][256] (n-major, K contiguous).
// Smem: both tiles [row][32 halves], pitch 40 halves (80 B, 20 words).
#define PW 20                           // pitch in 32-bit words
#define TILE_B (128 * PW * 4)           // 10240 B per tile
#define BUF_B  (2 * TILE_B)             // 20480 (A + B)
#define GEMM_SMEM (2 * BUF_B)           // 40960

__global__ void __launch_bounds__(256, 2)
k_gemm_f16(const __half* __restrict__ A, const __half* __restrict__ W,
           const float* __restrict__ bias, __half* __restrict__ C, int M) {
    extern __shared__ char smem[];
    uint32_t sb = smem_u32(smem);
    int tid = threadIdx.x;
    int lane = tid & 31, wid = tid >> 5;
    int warp_m = wid & 3, warp_n = wid >> 2;
    int g = lane >> 2, tig = lane & 3;
    int bm = blockIdx.x * 128;
    int bn = blockIdx.y * 128;

    float acc[2][8][4];
#pragma unroll
    for (int mt = 0; mt < 2; mt++)
#pragma unroll
        for (int nt = 0; nt < 8; nt++)
#pragma unroll
            for (int j = 0; j < 4; j++) acc[mt][nt][j] = 0.f;

    // per chunk: A tile 128x32 halves (4x16B per row), B tile 128(n)x32 halves
    auto load_chunk = [&](int c, int buf) {
        int k0 = c * 32;
        uint32_t abase = sb + buf * BUF_B;
        uint32_t bbase = abase + TILE_B;
#pragma unroll
        for (int i = 0; i < 2; i++) {
            int f = tid + i * 256;          // 0..511
            int r = f >> 2, q = f & 3;
            int gr = bm + r;
            const __half* src = A + (size_t)gr * HID + k0 + q * 8;
            uint32_t dst = abase + r * (PW * 4) + q * 16;
            uint32_t sz = (gr < M) ? 16u : 0u;
            CP_ASYNC16(dst, src, sz);
        }
#pragma unroll
        for (int i = 0; i < 2; i++) {
            int f = tid + i * 256;
            int r = f >> 2, q = f & 3;      // r = n row 0..127
            const __half* src = W + (size_t)(bn + r) * HID + k0 + q * 8;
            uint32_t dst = bbase + r * (PW * 4) + q * 16;
            CP_ASYNC16(dst, src, 16u);
        }
        CP_COMMIT();
    };

    load_chunk(0, 0);

    for (int c = 0; c < 8; c++) {
        int buf = c & 1;
        if (c < 7) {
            load_chunk(c + 1, buf ^ 1);
            CP_WAIT(1);
        } else {
            CP_WAIT(0);
        }
        __syncthreads();

        const uint32_t* As = (const uint32_t*)(smem + buf * BUF_B);
        const uint32_t* Bs = (const uint32_t*)(smem + buf * BUF_B + TILE_B);

#pragma unroll
        for (int ks = 0; ks < 2; ks++) {     // two k16 steps per 32-chunk
            int kw = ks * 8;                 // word offset
            uint32_t afr[2][4];
#pragma unroll
            for (int mt = 0; mt < 2; mt++) {
                int m0 = warp_m * 32 + mt * 16;
                afr[mt][0] = As[(m0 + g) * PW + kw + tig];
                afr[mt][1] = As[(m0 + 8 + g) * PW + kw + tig];
                afr[mt][2] = As[(m0 + g) * PW + kw + tig + 4];
                afr[mt][3] = As[(m0 + 8 + g) * PW + kw + tig + 4];
            }
            uint32_t bfr[8][2];
#pragma unroll
            for (int nt = 0; nt < 8; nt++) {
                int n0 = warp_n * 64 + nt * 8;
                bfr[nt][0] = Bs[(n0 + g) * PW + kw + tig];
                bfr[nt][1] = Bs[(n0 + g) * PW + kw + tig + 4];
            }
#pragma unroll
            for (int mt = 0; mt < 2; mt++)
#pragma unroll
                for (int nt = 0; nt < 8; nt++)
                    mma_f16(acc[mt][nt], afr[mt], bfr[nt]);
        }
        __syncthreads();
    }

    // epilogue: fp32 acc (+bias) -> fp16
#pragma unroll
    for (int mt = 0; mt < 2; mt++) {
        int m_base = bm + warp_m * 32 + mt * 16;
        int row0 = m_base + g;
        int row1 = m_base + 8 + g;
#pragma unroll
        for (int nt = 0; nt < 8; nt++) {
            int n = bn + warp_n * 64 + nt * 8 + 2 * tig;
            float2 badd = make_float2(0.f, 0.f);
            if (bias) badd = *(const float2*)&bias[n];
            if (row0 < M)
                *(__half2*)&C[(size_t)row0 * HID + n] =
                    __floats2half2_rn(acc[mt][nt][0] + badd.x, acc[mt][nt][1] + badd.y);
            if (row1 < M)
                *(__half2*)&C[(size_t)row1 * HID + n] =
                    __floats2half2_rn(acc[mt][nt][2] + badd.x, acc[mt][nt][3] + badd.y);
        }
    }
}

// ---------------- pull-based aggregation (fp16 in/out, fp32 accumulate) -------
// 64 threads/node, 4 nodes per 256-block, edge loop unrolled x2.
__global__ __launch_bounds__(256) void k_aggregate(const __half* __restrict__ h2,
                                                   const float* __restrict__ b,
                                                   __half* __restrict__ out) {
    int node = blockIdx.x * 4 + (threadIdx.x >> 6);
    int f4 = (threadIdx.x & 63) * 4;   // 4 halves per thread
    if (node >= N_NODES) return;

    int s = g_indptr[node];
    int e = g_indptr[node + 1];
    float dv = g_dinv[node];

    float4 acc = make_float4(0.f, 0.f, 0.f, 0.f);
    int i = s;
    for (; i + 1 < e; i += 2) {
        int s0 = g_csrsrc[i];
        int s1 = g_csrsrc[i + 1];
        float w0 = g_dinv[s0];
        float w1 = g_dinv[s1];
        uint2 p0 = *(const uint2*)&h2[(size_t)s0 * HID + f4];
        uint2 p1 = *(const uint2*)&h2[(size_t)s1 * HID + f4];
        float2 a0 = __half22float2(*(const __half2*)&p0.x);
        float2 c0 = __half22float2(*(const __half2*)&p0.y);
        float2 a1 = __half22float2(*(const __half2*)&p1.x);
        float2 c1 = __half22float2(*(const __half2*)&p1.y);
        acc.x += a0.x * w0 + a1.x * w1;
        acc.y += a0.y * w0 + a1.y * w1;
        acc.z += c0.x * w0 + c1.x * w1;
        acc.w += c0.y * w0 + c1.y * w1;
    }
    if (i < e) {
        int s0 = g_csrsrc[i];
        float w0 = g_dinv[s0];
        uint2 p0 = *(const uint2*)&h2[(size_t)s0 * HID + f4];
        float2 a0 = __half22float2(*(const __half2*)&p0.x);
        float2 c0 = __half22float2(*(const __half2*)&p0.y);
        acc.x += a0.x * w0;
        acc.y += a0.y * w0;
        acc.z += c0.x * w0;
        acc.w += c0.y * w0;
    }
    float4 bb = *(const float4*)&b[f4];
    uint2 o;
    *(__half2*)&o.x = __floats2half2_rn(fmaxf(acc.x * dv + bb.x, 0.f),
                                        fmaxf(acc.y * dv + bb.y, 0.f));
    *(__half2*)&o.y = __floats2half2_rn(fmaxf(acc.z * dv + bb.z, 0.f),
                                        fmaxf(acc.w * dv + bb.w, 0.f));
    *(uint2*)&out[(size_t)node * HID + f4] = o;
}

// ---------------- fused mean-pool + classifier --------------------------------
__global__ __launch_bounds__(256) void k_pool_cls(const __half* __restrict__ h,
                                                  const float* __restrict__ outW,
                                                  const float* __restrict__ outb,
                                                  float* __restrict__ out) {
    int g = blockIdx.x;
    int tid = threadIdx.x;
    __shared__ float sp[HID];

    int s = g_gstart[g];
    int e = g_gstart[g + 1];
    float acc = 0.f;
    for (int n = s; n < e; n++) acc += __half2float(h[(size_t)n * HID + tid]);
    float cnt = (float)(e - s);
    sp[tid] = acc / fmaxf(cnt, 1.0f);
    __syncthreads();

    if (tid < NCLASS) {
        float o = outb[tid];
#pragma unroll 8
        for (int f = 0; f < HID; f++) o += sp[f] * outW[f * NCLASS + tid];
        out[g * NCLASS + tid] = o;
    }
}

// ---------------- launch ------------------------------------------------------
extern "C" void kernel_launch(void* const* d_in, const int* in_sizes, int n_in,
                              void* d_out, int out_size) {
    const float* x      = (const float*)d_in[0];
    const int*   eidx   = (const int*)d_in[1];
    const int*   batch  = (const int*)d_in[2];
    const float* enc_W  = (const float*)d_in[3];
    const float* enc_b  = (const float*)d_in[4];
    const float* conv_W = (const float*)d_in[5];
    const float* conv_b = (const float*)d_in[6];
    const float* out_W  = (const float*)d_in[7];
    const float* out_b  = (const float*)d_in[8];
    float* out = (float*)d_out;

    const int* row = eidx;
    const int* col = eidx + E_EDGES;

    static cudaStream_t sB = nullptr;
    static cudaEvent_t evFork = nullptr, evCsr = nullptr;
    static bool init_done = false;
    if (!init_done) {
        cudaFuncSetAttribute(k_gemm_f16, cudaFuncAttributeMaxDynamicSharedMemorySize, GEMM_SMEM);
        cudaStreamCreateWithFlags(&sB, cudaStreamNonBlocking);
        cudaEventCreateWithFlags(&evFork, cudaEventDisableTiming);
        cudaEventCreateWithFlags(&evCsr, cudaEventDisableTiming);
        init_done = true;
    }

    __half* g_xh_ptr;   cudaGetSymbolAddress((void**)&g_xh_ptr,   g_xh);
    __half* g_hh_ptr;   cudaGetSymbolAddress((void**)&g_hh_ptr,   g_hh);
    __half* g_h2h_ptr;  cudaGetSymbolAddress((void**)&g_h2h_ptr,  g_h2h);
    __half* g_Wt16_ptr; cudaGetSymbolAddress((void**)&g_Wt16_ptr, g_Wt16);

    int nb = (N_NODES + 1023) / 1024;   // 49
    dim3 ggrid((N_NODES + 127) / 128, 2);

    // ---- fork: stream B builds CSR while stream 0 preps + runs GEMMs ---------
    cudaEventRecord(evFork, 0);
    cudaStreamWaitEvent(sB, evFork, 0);

    k_zero_deg<<<(N_NODES + 255) / 256, 256, 0, sB>>>();
    k_count_deg<<<2048, 256, 0, sB>>>(col);
    k_scan_local<<<nb, 1024, 0, sB>>>();
    k_scan_part<<<1, 64, 0, sB>>>();
    k_scan_add<<<nb, 1024, 0, sB>>>();
    k_fill_csr<<<2048, 256, 0, sB>>>(row, col);
    cudaEventRecord(evCsr, sB);

    // stream 0: conversions + encoder GEMM + layer-0 GEMM
    k_setup_w<<<(3 * HID * HID + 255) / 256, 256>>>(enc_W, conv_W, batch);
    k_conv_x<<<(N_NODES * HID / 4 + 255) / 256, 256>>>(x);
    k_gemm_f16<<<ggrid, 256, GEMM_SMEM>>>(g_xh_ptr, g_Wt16_ptr, enc_b, g_hh_ptr, N_NODES);
    k_gemm_f16<<<ggrid, 256, GEMM_SMEM>>>(g_hh_ptr, g_Wt16_ptr + HID * HID, nullptr, g_h2h_ptr, N_NODES);

    // join: first aggregation needs the CSR
    cudaStreamWaitEvent(0, evCsr, 0);

    k_aggregate<<<(N_NODES + 3) / 4, 256>>>(g_h2h_ptr, conv_b, g_hh_ptr);
    k_gemm_f16<<<ggrid, 256, GEMM_SMEM>>>(g_hh_ptr, g_Wt16_ptr + 2 * HID * HID, nullptr, g_h2h_ptr, N_NODES);
    k_aggregate<<<(N_NODES + 3) / 4, 256>>>(g_h2h_ptr, conv_b + HID, g_hh_ptr);
    k_pool_cls<<<NGRAPH, 256>>>(g_hh_ptr, out_W, out_b, out);
}

// round 14
// speedup vs baseline: 1.6427x; 1.0315x over previous
#include <cuda_runtime.h>
#include <cuda_fp16.h>
#include <math.h>
#include <stdint.h>

#define N_NODES 50000
#define E_EDGES 800000
#define HID 256
#define NCLASS 10
#define NGRAPH 512

// ---------------- device scratch (static; no cudaMalloc allowed) --------------
__device__ __half g_hh[(size_t)N_NODES * HID];    // fp16 activations
__device__ __half g_h2h[(size_t)N_NODES * HID];   // fp16 pre-agg
__device__ __half g_Wt16[HID * HID];              // conv_W[1] fp16, [N][K]
__device__ __half g_Wf16[HID * HID];              // fused We@Wc0 fp16, [N][K]
__device__ float  g_bf[HID];                      // fused bias be@Wc0
__device__ float  g_dinv[N_NODES];
__device__ int    g_deg[N_NODES];
__device__ int    g_indptr[N_NODES + 1];
__device__ int    g_cursor[N_NODES];
__device__ int    g_csrsrc[E_EDGES + N_NODES];
__device__ int    g_gstart[NGRAPH + 1];
__device__ int    g_part[64];

// ---------------- helpers -----------------------------------------------------
__device__ __forceinline__ uint32_t smem_u32(const void* p) {
    uint32_t a;
    asm("{ .reg .u64 t; cvta.to.shared.u64 t, %1; cvt.u32.u64 %0, t; }" : "=r"(a) : "l"(p));
    return a;
}
__device__ __forceinline__ uint32_t h2_bits(__half2 h) {
    return *(uint32_t*)&h;
}
__device__ __forceinline__ void mma_f16(float* d, const uint32_t* a, const uint32_t* b) {
    asm volatile(
        "mma.sync.aligned.m16n8k16.row.col.f32.f16.f16.f32 "
        "{%0,%1,%2,%3}, {%4,%5,%6,%7}, {%8,%9}, {%0,%1,%2,%3};"
        : "+f"(d[0]), "+f"(d[1]), "+f"(d[2]), "+f"(d[3])
        : "r"(a[0]), "r"(a[1]), "r"(a[2]), "r"(a[3]), "r"(b[0]), "r"(b[1]));
}
#define CP_ASYNC16(dst, src, sz) \
    asm volatile("cp.async.cg.shared.global [%0], [%1], 16, %2;" :: "r"(dst), "l"(src), "r"(sz))
#define CP_COMMIT()   asm volatile("cp.async.commit_group;" ::: "memory")
#define CP_WAIT(n)    asm volatile("cp.async.wait_group %0;" :: "n"(n) : "memory")

// ---------------- setup: layer-1 weights fp16 [N][K], gstart, fused bias ------
__global__ void k_setup_w(const float* __restrict__ conv_W, const float* __restrict__ enc_b,
                          const int* __restrict__ batch) {
    int id = blockIdx.x * blockDim.x + threadIdx.x;
    if (id < HID * HID) {   // conv_W[1] transpose -> fp16 [N][K]
        int k = id >> 8, n = id & 255;
        g_Wt16[n * HID + k] = __float2half_rn(conv_W[HID * HID + id]);
    }
    if (id < HID) {         // bf[n] = sum_j enc_b[j] * conv_W0[j][n]
        float acc = 0.f;
        for (int j = 0; j < HID; j++)
            acc += enc_b[j] * conv_W[j * HID + id];
        g_bf[id] = acc;
    }
    if (id <= NGRAPH) {
        int lo = 0, hi = N_NODES;
        while (lo < hi) {
            int mid = (lo + hi) >> 1;
            if (batch[mid] < id) lo = mid + 1; else hi = mid;
        }
        g_gstart[id] = lo;
    }
}

// fused weight: Wf[k][n] = sum_j We[k][j] * Wc0[j][n]; store fp16 transposed [n][k]
// grid (8,8), block 32x8, each thread does 4 output rows.
__global__ void k_fuse_w(const float* __restrict__ enc_W, const float* __restrict__ conv_W) {
    __shared__ float sA[32][33], sB[32][33];
    int tx = threadIdx.x, ty = threadIdx.y;       // 32 x 8
    int k0 = blockIdx.y * 32, n0 = blockIdx.x * 32;
    float acc[4] = {0.f, 0.f, 0.f, 0.f};
    for (int j0 = 0; j0 < HID; j0 += 32) {
#pragma unroll
        for (int r = 0; r < 4; r++) {
            sA[ty + r * 8][tx] = enc_W[(k0 + ty + r * 8) * HID + j0 + tx];
            sB[ty + r * 8][tx] = conv_W[(j0 + ty + r * 8) * HID + n0 + tx];
        }
        __syncthreads();
#pragma unroll
        for (int j = 0; j < 32; j++) {
            float b = sB[j][tx];
#pragma unroll
            for (int r = 0; r < 4; r++)
                acc[r] += sA[ty + r * 8][j] * b;
        }
        __syncthreads();
    }
#pragma unroll
    for (int r = 0; r < 4; r++)   // transposed store: [n][k]
        g_Wf16[(n0 + tx) * HID + k0 + ty + r * 8] = __float2half_rn(acc[r]);
}

// ---------------- CSR pipeline (stream B) -------------------------------------
__global__ void k_zero_deg() {
    int i = blockIdx.x * blockDim.x + threadIdx.x;
    if (i < N_NODES) g_deg[i] = 0;
}
__global__ void k_count_deg(const int* __restrict__ col) {
    int stride = gridDim.x * blockDim.x;
    for (int e = blockIdx.x * blockDim.x + threadIdx.x; e < E_EDGES; e += stride)
        atomicAdd(&g_deg[col[e]], 1);
}
__global__ void k_scan_local() {
    __shared__ int s[1024];
    int tid = threadIdx.x;
    int i = blockIdx.x * 1024 + tid;
    int v = 0;
    if (i < N_NODES) {
        int d = g_deg[i] + 1;
        v = d;
        g_dinv[i] = rsqrtf((float)d);
    }
    s[tid] = v;
    __syncthreads();
    for (int off = 1; off < 1024; off <<= 1) {
        int t = (tid >= off) ? s[tid - off] : 0;
        __syncthreads();
        s[tid] += t;
        __syncthreads();
    }
    if (i < N_NODES) g_indptr[i] = s[tid] - v;
    if (tid == 1023) g_part[blockIdx.x] = s[1023];
}
// add cross-block offsets; each block computes its own prefix of the 49 partials
__global__ void k_scan_add() {
    __shared__ int sp[64];
    __shared__ int soff;
    int tid = threadIdx.x;
    int nb = (N_NODES + 1023) / 1024;
    if (tid < 64) sp[tid] = (tid < nb) ? g_part[tid] : 0;
    __syncthreads();
    if (tid == 0) {
        int o = 0;
        for (int j = 0; j < blockIdx.x; j++) o += sp[j];
        soff = o;
    }
    __syncthreads();
    int i = blockIdx.x * 1024 + tid;
    if (i < N_NODES) {
        int v = g_indptr[i] + soff;
        g_indptr[i] = v;
        g_cursor[i] = v;
    }
    if (i == 0) g_indptr[N_NODES] = E_EDGES + N_NODES;
}
__global__ void k_fill_csr(const int* __restrict__ row, const int* __restrict__ col) {
    int stride = gridDim.x * blockDim.x;
    for (int t = blockIdx.x * blockDim.x + threadIdx.x; t < E_EDGES + N_NODES; t += stride) {
        int v, srcv;
        if (t < E_EDGES) { v = col[t]; srcv = row[t]; }
        else             { v = t - E_EDGES; srcv = v; }
        int p = atomicAdd(&g_cursor[v], 1);
        g_csrsrc[p] = srcv;
    }
}

// ---------------- mma.sync GEMM: [M,256] @ [256,256], templated A dtype -------
// Block 128x128, 8 warps (4x2), warp tile 32x64, K chunks of 32, cp.async DB.
// A fp16: [M][256] row-major, smem pitch 20 words. A fp32: pitch 36 words.
// W: fp16 [N][256] n-major. B smem pitch 20 words.
#define PWH 20
#define PWF 36
#define BTILE_B (128 * PWH * 4)                 // 10240
#define ATILE_H (128 * PWH * 4)                 // 10240
#define ATILE_F (128 * PWF * 4)                 // 18432
#define BUF_H (ATILE_H + BTILE_B)               // 20480
#define BUF_F (ATILE_F + BTILE_B)               // 28672
#define SMEM_H (2 * BUF_H)                      // 40960
#define SMEM_F (2 * BUF_F)                      // 57344

template <bool AFP32>
__global__ void __launch_bounds__(256, 2)
k_gemm(const void* __restrict__ Av, const __half* __restrict__ W,
       const float* __restrict__ bias, __half* __restrict__ C, int M) {
    extern __shared__ char smem[];
    uint32_t sb = smem_u32(smem);
    const int BUFB = AFP32 ? BUF_F : BUF_H;
    const int ATILE = AFP32 ? ATILE_F : ATILE_H;
    int tid = threadIdx.x;
    int lane = tid & 31, wid = tid >> 5;
    int warp_m = wid & 3, warp_n = wid >> 2;
    int g = lane >> 2, tig = lane & 3;
    int bm = blockIdx.x * 128;
    int bn = blockIdx.y * 128;

    float acc[2][8][4];
#pragma unroll
    for (int mt = 0; mt < 2; mt++)
#pragma unroll
        for (int nt = 0; nt < 8; nt++)
#pragma unroll
            for (int j = 0; j < 4; j++) acc[mt][nt][j] = 0.f;

    auto load_chunk = [&](int c, int buf) {
        int k0 = c * 32;
        uint32_t abase = sb + buf * BUFB;
        uint32_t bbase = abase + ATILE;
        if (AFP32) {
            const float* A = (const float*)Av;
#pragma unroll
            for (int i = 0; i < 4; i++) {
                int f = tid + i * 256;          // 0..1023
                int r = f >> 3, q = f & 7;
                int gr = bm + r;
                const float* src = A + (size_t)gr * HID + k0 + q * 4;
                uint32_t dst = abase + r * (PWF * 4) + q * 16;
                uint32_t sz = (gr < M) ? 16u : 0u;
                CP_ASYNC16(dst, src, sz);
            }
        } else {
            const __half* A = (const __half*)Av;
#pragma unroll
            for (int i = 0; i < 2; i++) {
                int f = tid + i * 256;          // 0..511
                int r = f >> 2, q = f & 3;
                int gr = bm + r;
                const __half* src = A + (size_t)gr * HID + k0 + q * 8;
                uint32_t dst = abase + r * (PWH * 4) + q * 16;
                uint32_t sz = (gr < M) ? 16u : 0u;
                CP_ASYNC16(dst, src, sz);
            }
        }
#pragma unroll
        for (int i = 0; i < 2; i++) {
            int f = tid + i * 256;
            int r = f >> 2, q = f & 3;          // n row 0..127
            const __half* src = W + (size_t)(bn + r) * HID + k0 + q * 8;
            uint32_t dst = bbase + r * (PWH * 4) + q * 16;
            CP_ASYNC16(dst, src, 16u);
        }
        CP_COMMIT();
    };

    load_chunk(0, 0);

    for (int c = 0; c < 8; c++) {
        int buf = c & 1;
        if (c < 7) {
            load_chunk(c + 1, buf ^ 1);
            CP_WAIT(1);
        } else {
            CP_WAIT(0);
        }
        __syncthreads();

        const char* base = smem + buf * BUFB;
        const uint32_t* Bs = (const uint32_t*)(base + ATILE);

#pragma unroll
        for (int ks = 0; ks < 2; ks++) {
            uint32_t afr[2][4];
            if (AFP32) {
                const float* Asf = (const float*)base;
                int ke = ks * 16 + 2 * tig;      // k element index
#pragma unroll
                for (int mt = 0; mt < 2; mt++) {
                    int m0 = warp_m * 32 + mt * 16;
                    float2 v0 = *(const float2*)&Asf[(m0 + g) * PWF + ke];
                    float2 v1 = *(const float2*)&Asf[(m0 + 8 + g) * PWF + ke];
                    float2 v2 = *(const float2*)&Asf[(m0 + g) * PWF + ke + 8];
                    float2 v3 = *(const float2*)&Asf[(m0 + 8 + g) * PWF + ke + 8];
                    afr[mt][0] = h2_bits(__floats2half2_rn(v0.x, v0.y));
                    afr[mt][1] = h2_bits(__floats2half2_rn(v1.x, v1.y));
                    afr[mt][2] = h2_bits(__floats2half2_rn(v2.x, v2.y));
                    afr[mt][3] = h2_bits(__floats2half2_rn(v3.x, v3.y));
                }
            } else {
                const uint32_t* As = (const uint32_t*)base;
                int kw = ks * 8;
#pragma unroll
                for (int mt = 0; mt < 2; mt++) {
                    int m0 = warp_m * 32 + mt * 16;
                    afr[mt][0] = As[(m0 + g) * PWH + kw + tig];
                    afr[mt][1] = As[(m0 + 8 + g) * PWH + kw + tig];
                    afr[mt][2] = As[(m0 + g) * PWH + kw + tig + 4];
                    afr[mt][3] = As[(m0 + 8 + g) * PWH + kw + tig + 4];
                }
            }
            int kw = ks * 8;
            uint32_t bfr[8][2];
#pragma unroll
            for (int nt = 0; nt < 8; nt++) {
                int n0 = warp_n * 64 + nt * 8;
                bfr[nt][0] = Bs[(n0 + g) * PWH + kw + tig];
                bfr[nt][1] = Bs[(n0 + g) * PWH + kw + tig + 4];
            }
#pragma unroll
            for (int mt = 0; mt < 2; mt++)
#pragma unroll
                for (int nt = 0; nt < 8; nt++)
                    mma_f16(acc[mt][nt], afr[mt], bfr[nt]);
        }
        __syncthreads();
    }

    // epilogue: fp32 acc (+bias) -> fp16
#pragma unroll
    for (int mt = 0; mt < 2; mt++) {
        int m_base = bm + warp_m * 32 + mt * 16;
        int row0 = m_base + g;
        int row1 = m_base + 8 + g;
#pragma unroll
        for (int nt = 0; nt < 8; nt++) {
            int n = bn + warp_n * 64 + nt * 8 + 2 * tig;
            float2 badd = make_float2(0.f, 0.f);
            if (bias) badd = *(const float2*)&bias[n];
            if (row0 < M)
                *(__half2*)&C[(size_t)row0 * HID + n] =
                    __floats2half2_rn(acc[mt][nt][0] + badd.x, acc[mt][nt][1] + badd.y);
            if (row1 < M)
                *(__half2*)&C[(size_t)row1 * HID + n] =
                    __floats2half2_rn(acc[mt][nt][2] + badd.x, acc[mt][nt][3] + badd.y);
        }
    }
}

// ---------------- pull-based aggregation (fp16 in/out, fp32 accumulate) -------
__global__ __launch_bounds__(256) void k_aggregate(const __half* __restrict__ h2,
                                                   const float* __restrict__ b,
                                                   __half* __restrict__ out) {
    int node = blockIdx.x * 4 + (threadIdx.x >> 6);
    int f4 = (threadIdx.x & 63) * 4;
    if (node >= N_NODES) return;

    int s = g_indptr[node];
    int e = g_indptr[node + 1];
    float dv = g_dinv[node];

    float4 acc = make_float4(0.f, 0.f, 0.f, 0.f);
    int i = s;
    for (; i + 1 < e; i += 2) {
        int s0 = g_csrsrc[i];
        int s1 = g_csrsrc[i + 1];
        float w0 = g_dinv[s0];
        float w1 = g_dinv[s1];
        uint2 p0 = *(const uint2*)&h2[(size_t)s0 * HID + f4];
        uint2 p1 = *(const uint2*)&h2[(size_t)s1 * HID + f4];
        float2 a0 = __half22float2(*(const __half2*)&p0.x);
        float2 c0 = __half22float2(*(const __half2*)&p0.y);
        float2 a1 = __half22float2(*(const __half2*)&p1.x);
        float2 c1 = __half22float2(*(const __half2*)&p1.y);
        acc.x += a0.x * w0 + a1.x * w1;
        acc.y += a0.y * w0 + a1.y * w1;
        acc.z += c0.x * w0 + c1.x * w1;
        acc.w += c0.y * w0 + c1.y * w1;
    }
    if (i < e) {
        int s0 = g_csrsrc[i];
        float w0 = g_dinv[s0];
        uint2 p0 = *(const uint2*)&h2[(size_t)s0 * HID + f4];
        float2 a0 = __half22float2(*(const __half2*)&p0.x);
        float2 c0 = __half22float2(*(const __half2*)&p0.y);
        acc.x += a0.x * w0;
        acc.y += a0.y * w0;
        acc.z += c0.x * w0;
        acc.w += c0.y * w0;
    }
    float4 bb = *(const float4*)&b[f4];
    uint2 o;
    *(__half2*)&o.x = __floats2half2_rn(fmaxf(acc.x * dv + bb.x, 0.f),
                                        fmaxf(acc.y * dv + bb.y, 0.f));
    *(__half2*)&o.y = __floats2half2_rn(fmaxf(acc.z * dv + bb.z, 0.f),
                                        fmaxf(acc.w * dv + bb.w, 0.f));
    *(uint2*)&out[(size_t)node * HID + f4] = o;
}

// ---------------- fused mean-pool + classifier --------------------------------
__global__ __launch_bounds__(256) void k_pool_cls(const __half* __restrict__ h,
                                                  const float* __restrict__ outW,
                                                  const float* __restrict__ outb,
                                                  float* __restrict__ out) {
    int g = blockIdx.x;
    int tid = threadIdx.x;
    __shared__ float sp[HID];

    int s = g_gstart[g];
    int e = g_gstart[g + 1];
    float acc = 0.f;
    for (int n = s; n < e; n++) acc += __half2float(h[(size_t)n * HID + tid]);
    float cnt = (float)(e - s);
    sp[tid] = acc / fmaxf(cnt, 1.0f);
    __syncthreads();

    if (tid < NCLASS) {
        float o = outb[tid];
#pragma unroll 8
        for (int f = 0; f < HID; f++) o += sp[f] * outW[f * NCLASS + tid];
        out[g * NCLASS + tid] = o;
    }
}

// ---------------- launch ------------------------------------------------------
extern "C" void kernel_launch(void* const* d_in, const int* in_sizes, int n_in,
                              void* d_out, int out_size) {
    const float* x      = (const float*)d_in[0];
    const int*   eidx   = (const int*)d_in[1];
    const int*   batch  = (const int*)d_in[2];
    const float* enc_W  = (const float*)d_in[3];
    const float* enc_b  = (const float*)d_in[4];
    const float* conv_W = (const float*)d_in[5];
    const float* conv_b = (const float*)d_in[6];
    const float* out_W  = (const float*)d_in[7];
    const float* out_b  = (const float*)d_in[8];
    float* out = (float*)d_out;

    const int* row = eidx;
    const int* col = eidx + E_EDGES;

    static cudaStream_t sB = nullptr;
    static cudaEvent_t evFork = nullptr, evCsr = nullptr;
    static bool init_done = false;
    if (!init_done) {
        cudaFuncSetAttribute(k_gemm<true>,  cudaFuncAttributeMaxDynamicSharedMemorySize, SMEM_F);
        cudaFuncSetAttribute(k_gemm<false>, cudaFuncAttributeMaxDynamicSharedMemorySize, SMEM_H);
        cudaStreamCreateWithFlags(&sB, cudaStreamNonBlocking);
        cudaEventCreateWithFlags(&evFork, cudaEventDisableTiming);
        cudaEventCreateWithFlags(&evCsr, cudaEventDisableTiming);
        init_done = true;
    }

    __half* g_hh_ptr;   cudaGetSymbolAddress((void**)&g_hh_ptr,   g_hh);
    __half* g_h2h_ptr;  cudaGetSymbolAddress((void**)&g_h2h_ptr,  g_h2h);
    __half* g_Wt16_ptr; cudaGetSymbolAddress((void**)&g_Wt16_ptr, g_Wt16);
    __half* g_Wf16_ptr; cudaGetSymbolAddress((void**)&g_Wf16_ptr, g_Wf16);
    float*  g_bf_ptr;   cudaGetSymbolAddress((void**)&g_bf_ptr,   g_bf);

    int nb = (N_NODES + 1023) / 1024;   // 49
    dim3 ggrid((N_NODES + 127) / 128, 2);

    // ---- fork: stream B builds CSR while stream 0 preps + runs fused GEMM ----
    cudaEventRecord(evFork, 0);
    cudaStreamWaitEvent(sB, evFork, 0);

    k_zero_deg<<<(N_NODES + 255) / 256, 256, 0, sB>>>();
    k_count_deg<<<2048, 256, 0, sB>>>(col);
    k_scan_local<<<nb, 1024, 0, sB>>>();
    k_scan_add<<<nb, 1024, 0, sB>>>();
    k_fill_csr<<<2048, 256, 0, sB>>>(row, col);
    cudaEventRecord(evCsr, sB);

    // stream 0: weight prep + fused encoder+layer0 GEMM (fp32 A)
    k_setup_w<<<(HID * HID + 255) / 256, 256>>>(conv_W, enc_b, batch);
    k_fuse_w<<<dim3(8, 8), dim3(32, 8)>>>(enc_W, conv_W);
    k_gemm<true><<<ggrid, 256, SMEM_F>>>(x, g_Wf16_ptr, g_bf_ptr, g_h2h_ptr, N_NODES);

    // join: first aggregation needs the CSR
    cudaStreamWaitEvent(0, evCsr, 0);

    k_aggregate<<<(N_NODES + 3) / 4, 256>>>(g_h2h_ptr, conv_b, g_hh_ptr);
    k_gemm<false><<<ggrid, 256, SMEM_H>>>(g_hh_ptr, g_Wt16_ptr, nullptr, g_h2h_ptr, N_NODES);
    k_aggregate<<<(N_NODES + 3) / 4, 256>>>(g_h2h_ptr, conv_b + HID, g_hh_ptr);
    k_pool_cls<<<NGRAPH, 256>>>(g_hh_ptr, out_W, out_b, out);
}

// round 15
// speedup vs baseline: 1.6881x; 1.0277x over previous
#include <cuda_runtime.h>
#include <cuda_fp16.h>
#include <cuda_fp8.h>
#include <math.h>
#include <stdint.h>

#define N_NODES 50000
#define E_EDGES 800000
#define HID 256
#define NCLASS 10
#define NGRAPH 512

// ---------------- device scratch (static; no cudaMalloc allowed) --------------
__device__ __half  g_hh[(size_t)N_NODES * HID];     // fp16 activations (agg out)
__device__ uint8_t g_h2q[(size_t)N_NODES * HID];    // fp8 e4m3 pre-agg (dinv-scaled)
__device__ __half  g_Wt16[HID * HID];               // conv_W[1] fp16, [N][K]
__device__ __half  g_Wf16[HID * HID];               // fused We@Wc0 fp16, [N][K]
__device__ float   g_bf[HID];                       // fused bias be@Wc0
__device__ float   g_dinv[N_NODES];
__device__ int     g_deg[N_NODES];
__device__ int     g_indptr[N_NODES + 1];
__device__ int     g_cursor[N_NODES];
__device__ int     g_csrsrc[E_EDGES + N_NODES];
__device__ int     g_gstart[NGRAPH + 1];
__device__ int     g_part[64];

// ---------------- helpers -----------------------------------------------------
__device__ __forceinline__ uint32_t smem_u32(const void* p) {
    uint32_t a;
    asm("{ .reg .u64 t; cvta.to.shared.u64 t, %1; cvt.u32.u64 %0, t; }" : "=r"(a) : "l"(p));
    return a;
}
__device__ __forceinline__ uint32_t h2_bits(__half2 h) {
    return *(uint32_t*)&h;
}
__device__ __forceinline__ void mma_f16(float* d, const uint32_t* a, const uint32_t* b) {
    asm volatile(
        "mma.sync.aligned.m16n8k16.row.col.f32.f16.f16.f32 "
        "{%0,%1,%2,%3}, {%4,%5,%6,%7}, {%8,%9}, {%0,%1,%2,%3};"
        : "+f"(d[0]), "+f"(d[1]), "+f"(d[2]), "+f"(d[3])
        : "r"(a[0]), "r"(a[1]), "r"(a[2]), "r"(a[3]), "r"(b[0]), "r"(b[1]));
}
#define CP_ASYNC16(dst, src, sz) \
    asm volatile("cp.async.cg.shared.global [%0], [%1], 16, %2;" :: "r"(dst), "l"(src), "r"(sz))
#define CP_COMMIT()   asm volatile("cp.async.commit_group;" ::: "memory")
#define CP_WAIT(n)    asm volatile("cp.async.wait_group %0;" :: "n"(n) : "memory")

// ---------------- setup: layer-1 weights fp16 [N][K], gstart, fused bias ------
__global__ void k_setup_w(const float* __restrict__ conv_W, const float* __restrict__ enc_b,
                          const int* __restrict__ batch) {
    int id = blockIdx.x * blockDim.x + threadIdx.x;
    if (id < HID * HID) {   // conv_W[1] transpose -> fp16 [N][K]
        int k = id >> 8, n = id & 255;
        g_Wt16[n * HID + k] = __float2half_rn(conv_W[HID * HID + id]);
    }
    if (id < HID) {         // bf[n] = sum_j enc_b[j] * conv_W0[j][n]
        float acc = 0.f;
        for (int j = 0; j < HID; j++)
            acc += enc_b[j] * conv_W[j * HID + id];
        g_bf[id] = acc;
    }
    if (id <= NGRAPH) {
        int lo = 0, hi = N_NODES;
        while (lo < hi) {
            int mid = (lo + hi) >> 1;
            if (batch[mid] < id) lo = mid + 1; else hi = mid;
        }
        g_gstart[id] = lo;
    }
}

// fused weight: Wf[k][n] = sum_j We[k][j] * Wc0[j][n]; store fp16 transposed [n][k]
__global__ void k_fuse_w(const float* __restrict__ enc_W, const float* __restrict__ conv_W) {
    __shared__ float sA[32][33], sB[32][33];
    int tx = threadIdx.x, ty = threadIdx.y;       // 32 x 8
    int k0 = blockIdx.y * 32, n0 = blockIdx.x * 32;
    float acc[4] = {0.f, 0.f, 0.f, 0.f};
    for (int j0 = 0; j0 < HID; j0 += 32) {
#pragma unroll
        for (int r = 0; r < 4; r++) {
            sA[ty + r * 8][tx] = enc_W[(k0 + ty + r * 8) * HID + j0 + tx];
            sB[ty + r * 8][tx] = conv_W[(j0 + ty + r * 8) * HID + n0 + tx];
        }
        __syncthreads();
#pragma unroll
        for (int j = 0; j < 32; j++) {
            float b = sB[j][tx];
#pragma unroll
            for (int r = 0; r < 4; r++)
                acc[r] += sA[ty + r * 8][j] * b;
        }
        __syncthreads();
    }
#pragma unroll
    for (int r = 0; r < 4; r++)   // transposed store: [n][k]
        g_Wf16[(n0 + tx) * HID + k0 + ty + r * 8] = __float2half_rn(acc[r]);
}

// ---------------- CSR pipeline (stream B) -------------------------------------
__global__ void k_zero_deg() {
    int i = blockIdx.x * blockDim.x + threadIdx.x;
    if (i < N_NODES) g_deg[i] = 0;
}
__global__ void k_count_deg(const int* __restrict__ col) {
    int stride = gridDim.x * blockDim.x;
    for (int e = blockIdx.x * blockDim.x + threadIdx.x; e < E_EDGES; e += stride)
        atomicAdd(&g_deg[col[e]], 1);
}
__global__ void k_scan_local() {
    __shared__ int s[1024];
    int tid = threadIdx.x;
    int i = blockIdx.x * 1024 + tid;
    int v = 0;
    if (i < N_NODES) {
        int d = g_deg[i] + 1;
        v = d;
        g_dinv[i] = rsqrtf((float)d);
    }
    s[tid] = v;
    __syncthreads();
    for (int off = 1; off < 1024; off <<= 1) {
        int t = (tid >= off) ? s[tid - off] : 0;
        __syncthreads();
        s[tid] += t;
        __syncthreads();
    }
    if (i < N_NODES) g_indptr[i] = s[tid] - v;
    if (tid == 1023) g_part[blockIdx.x] = s[1023];
}
// add cross-block offsets; each block computes its own prefix of the 49 partials
__global__ void k_scan_add() {
    __shared__ int sp[64];
    __shared__ int soff;
    int tid = threadIdx.x;
    int nb = (N_NODES + 1023) / 1024;
    if (tid < 64) sp[tid] = (tid < nb) ? g_part[tid] : 0;
    __syncthreads();
    if (tid == 0) {
        int o = 0;
        for (int j = 0; j < blockIdx.x; j++) o += sp[j];
        soff = o;
    }
    __syncthreads();
    int i = blockIdx.x * 1024 + tid;
    if (i < N_NODES) {
        int v = g_indptr[i] + soff;
        g_indptr[i] = v;
        g_cursor[i] = v;
    }
    if (i == 0) g_indptr[N_NODES] = E_EDGES + N_NODES;
}
__global__ void k_fill_csr(const int* __restrict__ row, const int* __restrict__ col) {
    int stride = gridDim.x * blockDim.x;
    for (int t = blockIdx.x * blockDim.x + threadIdx.x; t < E_EDGES + N_NODES; t += stride) {
        int v, srcv;
        if (t < E_EDGES) { v = col[t]; srcv = row[t]; }
        else             { v = t - E_EDGES; srcv = v; }
        int p = atomicAdd(&g_cursor[v], 1);
        g_csrsrc[p] = srcv;
    }
}

// ---------------- mma.sync GEMM: [M,256] @ [256,256], templated A dtype -------
// Output: fp8 e4m3, value = (acc [+ bias]) * dinv[row]   (pre-scaled for agg)
#define PWH 20
#define PWF 36
#define BTILE_B (128 * PWH * 4)                 // 10240
#define ATILE_H (128 * PWH * 4)                 // 10240
#define ATILE_F (128 * PWF * 4)                 // 18432
#define BUF_H (ATILE_H + BTILE_B)               // 20480
#define BUF_F (ATILE_F + BTILE_B)               // 28672
#define SMEM_H (2 * BUF_H)                      // 40960
#define SMEM_F (2 * BUF_F)                      // 57344

template <bool AFP32>
__global__ void __launch_bounds__(256, 2)
k_gemm(const void* __restrict__ Av, const __half* __restrict__ W,
       const float* __restrict__ bias, uint8_t* __restrict__ C8, int M) {
    extern __shared__ char smem[];
    uint32_t sb = smem_u32(smem);
    const int BUFB = AFP32 ? BUF_F : BUF_H;
    const int ATILE = AFP32 ? ATILE_F : ATILE_H;
    int tid = threadIdx.x;
    int lane = tid & 31, wid = tid >> 5;
    int warp_m = wid & 3, warp_n = wid >> 2;
    int g = lane >> 2, tig = lane & 3;
    int bm = blockIdx.x * 128;
    int bn = blockIdx.y * 128;

    float acc[2][8][4];
#pragma unroll
    for (int mt = 0; mt < 2; mt++)
#pragma unroll
        for (int nt = 0; nt < 8; nt++)
#pragma unroll
            for (int j = 0; j < 4; j++) acc[mt][nt][j] = 0.f;

    auto load_chunk = [&](int c, int buf) {
        int k0 = c * 32;
        uint32_t abase = sb + buf * BUFB;
        uint32_t bbase = abase + ATILE;
        if (AFP32) {
            const float* A = (const float*)Av;
#pragma unroll
            for (int i = 0; i < 4; i++) {
                int f = tid + i * 256;          // 0..1023
                int r = f >> 3, q = f & 7;
                int gr = bm + r;
                const float* src = A + (size_t)gr * HID + k0 + q * 4;
                uint32_t dst = abase + r * (PWF * 4) + q * 16;
                uint32_t sz = (gr < M) ? 16u : 0u;
                CP_ASYNC16(dst, src, sz);
            }
        } else {
            const __half* A = (const __half*)Av;
#pragma unroll
            for (int i = 0; i < 2; i++) {
                int f = tid + i * 256;          // 0..511
                int r = f >> 2, q = f & 3;
                int gr = bm + r;
                const __half* src = A + (size_t)gr * HID + k0 + q * 8;
                uint32_t dst = abase + r * (PWH * 4) + q * 16;
                uint32_t sz = (gr < M) ? 16u : 0u;
                CP_ASYNC16(dst, src, sz);
            }
        }
#pragma unroll
        for (int i = 0; i < 2; i++) {
            int f = tid + i * 256;
            int r = f >> 2, q = f & 3;          // n row 0..127
            const __half* src = W + (size_t)(bn + r) * HID + k0 + q * 8;
            uint32_t dst = bbase + r * (PWH * 4) + q * 16;
            CP_ASYNC16(dst, src, 16u);
        }
        CP_COMMIT();
    };

    load_chunk(0, 0);

    for (int c = 0; c < 8; c++) {
        int buf = c & 1;
        if (c < 7) {
            load_chunk(c + 1, buf ^ 1);
            CP_WAIT(1);
        } else {
            CP_WAIT(0);
        }
        __syncthreads();

        const char* base = smem + buf * BUFB;
        const uint32_t* Bs = (const uint32_t*)(base + ATILE);

#pragma unroll
        for (int ks = 0; ks < 2; ks++) {
            uint32_t afr[2][4];
            if (AFP32) {
                const float* Asf = (const float*)base;
                int ke = ks * 16 + 2 * tig;      // k element index
#pragma unroll
                for (int mt = 0; mt < 2; mt++) {
                    int m0 = warp_m * 32 + mt * 16;
                    float2 v0 = *(const float2*)&Asf[(m0 + g) * PWF + ke];
                    float2 v1 = *(const float2*)&Asf[(m0 + 8 + g) * PWF + ke];
                    float2 v2 = *(const float2*)&Asf[(m0 + g) * PWF + ke + 8];
                    float2 v3 = *(const float2*)&Asf[(m0 + 8 + g) * PWF + ke + 8];
                    afr[mt][0] = h2_bits(__floats2half2_rn(v0.x, v0.y));
                    afr[mt][1] = h2_bits(__floats2half2_rn(v1.x, v1.y));
                    afr[mt][2] = h2_bits(__floats2half2_rn(v2.x, v2.y));
                    afr[mt][3] = h2_bits(__floats2half2_rn(v3.x, v3.y));
                }
            } else {
                const uint32_t* As = (const uint32_t*)base;
                int kw = ks * 8;
#pragma unroll
                for (int mt = 0; mt < 2; mt++) {
                    int m0 = warp_m * 32 + mt * 16;
                    afr[mt][0] = As[(m0 + g) * PWH + kw + tig];
                    afr[mt][1] = As[(m0 + 8 + g) * PWH + kw + tig];
                    afr[mt][2] = As[(m0 + g) * PWH + kw + tig + 4];
                    afr[mt][3] = As[(m0 + 8 + g) * PWH + kw + tig + 4];
                }
            }
            int kw = ks * 8;
            uint32_t bfr[8][2];
#pragma unroll
            for (int nt = 0; nt < 8; nt++) {
                int n0 = warp_n * 64 + nt * 8;
                bfr[nt][0] = Bs[(n0 + g) * PWH + kw + tig];
                bfr[nt][1] = Bs[(n0 + g) * PWH + kw + tig + 4];
            }
#pragma unroll
            for (int mt = 0; mt < 2; mt++)
#pragma unroll
                for (int nt = 0; nt < 8; nt++)
                    mma_f16(acc[mt][nt], afr[mt], bfr[nt]);
        }
        __syncthreads();
    }

    // epilogue: (acc [+ bias]) * dinv[row] -> fp8 e4m3
#pragma unroll
    for (int mt = 0; mt < 2; mt++) {
        int m_base = bm + warp_m * 32 + mt * 16;
        int row0 = m_base + g;
        int row1 = m_base + 8 + g;
        float s0 = (row0 < M) ? g_dinv[row0] : 0.f;
        float s1 = (row1 < M) ? g_dinv[row1] : 0.f;
#pragma unroll
        for (int nt = 0; nt < 8; nt++) {
            int n = bn + warp_n * 64 + nt * 8 + 2 * tig;
            float2 badd = make_float2(0.f, 0.f);
            if (bias) badd = *(const float2*)&bias[n];
            if (row0 < M) {
                float2 v = make_float2((acc[mt][nt][0] + badd.x) * s0,
                                       (acc[mt][nt][1] + badd.y) * s0);
                __nv_fp8x2_storage_t p = __nv_cvt_float2_to_fp8x2(v, __NV_SATFINITE, __NV_E4M3);
                *(unsigned short*)&C8[(size_t)row0 * HID + n] = p;
            }
            if (row1 < M) {
                float2 v = make_float2((acc[mt][nt][2] + badd.x) * s1,
                                       (acc[mt][nt][3] + badd.y) * s1);
                __nv_fp8x2_storage_t p = __nv_cvt_float2_to_fp8x2(v, __NV_SATFINITE, __NV_E4M3);
                *(unsigned short*)&C8[(size_t)row1 * HID + n] = p;
            }
        }
    }
}

// ---------------- pull-based aggregation (fp8 gather, fp32 accumulate) --------
// rows already scaled by dinv[src]; out = relu(dinv[v]*sum + b) in fp16.
// 64 threads/node, 4 nodes per 256-block, edge loop unrolled x2.
__global__ __launch_bounds__(256) void k_aggregate(const uint8_t* __restrict__ q,
                                                   const float* __restrict__ b,
                                                   __half* __restrict__ out) {
    int node = blockIdx.x * 4 + (threadIdx.x >> 6);
    int f4 = (threadIdx.x & 63) * 4;   // 4 fp8 per thread
    if (node >= N_NODES) return;

    int s = g_indptr[node];
    int e = g_indptr[node + 1];
    float dv = g_dinv[node];

    float4 acc = make_float4(0.f, 0.f, 0.f, 0.f);
    int i = s;
    for (; i + 1 < e; i += 2) {
        int s0 = g_csrsrc[i];
        int s1 = g_csrsrc[i + 1];
        uint32_t u0 = *(const uint32_t*)&q[(size_t)s0 * HID + f4];
        uint32_t u1 = *(const uint32_t*)&q[(size_t)s1 * HID + f4];
        __half2_raw l0 = __nv_cvt_fp8x2_to_halfraw2((__nv_fp8x2_storage_t)(u0 & 0xFFFF), __NV_E4M3);
        __half2_raw h0 = __nv_cvt_fp8x2_to_halfraw2((__nv_fp8x2_storage_t)(u0 >> 16), __NV_E4M3);
        __half2_raw l1 = __nv_cvt_fp8x2_to_halfraw2((__nv_fp8x2_storage_t)(u1 & 0xFFFF), __NV_E4M3);
        __half2_raw h1 = __nv_cvt_fp8x2_to_halfraw2((__nv_fp8x2_storage_t)(u1 >> 16), __NV_E4M3);
        float2 a0 = __half22float2(*(__half2*)&l0);
        float2 c0 = __half22float2(*(__half2*)&h0);
        float2 a1 = __half22float2(*(__half2*)&l1);
        float2 c1 = __half22float2(*(__half2*)&h1);
        acc.x += a0.x + a1.x;
        acc.y += a0.y + a1.y;
        acc.z += c0.x + c1.x;
        acc.w += c0.y + c1.y;
    }
    if (i < e) {
        int s0 = g_csrsrc[i];
        uint32_t u0 = *(const uint32_t*)&q[(size_t)s0 * HID + f4];
        __half2_raw l0 = __nv_cvt_fp8x2_to_halfraw2((__nv_fp8x2_storage_t)(u0 & 0xFFFF), __NV_E4M3);
        __half2_raw h0 = __nv_cvt_fp8x2_to_halfraw2((__nv_fp8x2_storage_t)(u0 >> 16), __NV_E4M3);
        float2 a0 = __half22float2(*(__half2*)&l0);
        float2 c0 = __half22float2(*(__half2*)&h0);
        acc.x += a0.x;
        acc.y += a0.y;
        acc.z += c0.x;
        acc.w += c0.y;
    }
    float4 bb = *(const float4*)&b[f4];
    uint2 o;
    *(__half2*)&o.x = __floats2half2_rn(fmaxf(acc.x * dv + bb.x, 0.f),
                                        fmaxf(acc.y * dv + bb.y, 0.f));
    *(__half2*)&o.y = __floats2half2_rn(fmaxf(acc.z * dv + bb.z, 0.f),
                                        fmaxf(acc.w * dv + bb.w, 0.f));
    *(uint2*)&out[(size_t)node * HID + f4] = o;
}

// ---------------- fused mean-pool + classifier --------------------------------
__global__ __launch_bounds__(256) void k_pool_cls(const __half* __restrict__ h,
                                                  const float* __restrict__ outW,
                                                  const float* __restrict__ outb,
                                                  float* __restrict__ out) {
    int g = blockIdx.x;
    int tid = threadIdx.x;
    __shared__ float sp[HID];

    int s = g_gstart[g];
    int e = g_gstart[g + 1];
    float acc = 0.f;
    for (int n = s; n < e; n++) acc += __half2float(h[(size_t)n * HID + tid]);
    float cnt = (float)(e - s);
    sp[tid] = acc / fmaxf(cnt, 1.0f);
    __syncthreads();

    if (tid < NCLASS) {
        float o = outb[tid];
#pragma unroll 8
        for (int f = 0; f < HID; f++) o += sp[f] * outW[f * NCLASS + tid];
        out[g * NCLASS + tid] = o;
    }
}

// ---------------- launch ------------------------------------------------------
extern "C" void kernel_launch(void* const* d_in, const int* in_sizes, int n_in,
                              void* d_out, int out_size) {
    const float* x      = (const float*)d_in[0];
    const int*   eidx   = (const int*)d_in[1];
    const int*   batch  = (const int*)d_in[2];
    const float* enc_W  = (const float*)d_in[3];
    const float* enc_b  = (const float*)d_in[4];
    const float* conv_W = (const float*)d_in[5];
    const float* conv_b = (const float*)d_in[6];
    const float* out_W  = (const float*)d_in[7];
    const float* out_b  = (const float*)d_in[8];
    float* out = (float*)d_out;

    const int* row = eidx;
    const int* col = eidx + E_EDGES;

    static cudaStream_t sB = nullptr;
    static cudaEvent_t evFork = nullptr, evDinv = nullptr, evCsr = nullptr;
    static bool init_done = false;
    if (!init_done) {
        cudaFuncSetAttribute(k_gemm<true>,  cudaFuncAttributeMaxDynamicSharedMemorySize, SMEM_F);
        cudaFuncSetAttribute(k_gemm<false>, cudaFuncAttributeMaxDynamicSharedMemorySize, SMEM_H);
        cudaStreamCreateWithFlags(&sB, cudaStreamNonBlocking);
        cudaEventCreateWithFlags(&evFork, cudaEventDisableTiming);
        cudaEventCreateWithFlags(&evDinv, cudaEventDisableTiming);
        cudaEventCreateWithFlags(&evCsr, cudaEventDisableTiming);
        init_done = true;
    }

    __half*  g_hh_ptr;   cudaGetSymbolAddress((void**)&g_hh_ptr,   g_hh);
    uint8_t* g_h2q_ptr;  cudaGetSymbolAddress((void**)&g_h2q_ptr,  g_h2q);
    __half*  g_Wt16_ptr; cudaGetSymbolAddress((void**)&g_Wt16_ptr, g_Wt16);
    __half*  g_Wf16_ptr; cudaGetSymbolAddress((void**)&g_Wf16_ptr, g_Wf16);
    float*   g_bf_ptr;   cudaGetSymbolAddress((void**)&g_bf_ptr,   g_bf);

    int nb = (N_NODES + 1023) / 1024;   // 49
    dim3 ggrid((N_NODES + 127) / 128, 2);

    // ---- fork: stream B builds degrees/CSR; stream 0 preps weights -----------
    cudaEventRecord(evFork, 0);
    cudaStreamWaitEvent(sB, evFork, 0);

    k_zero_deg<<<(N_NODES + 255) / 256, 256, 0, sB>>>();
    k_count_deg<<<2048, 256, 0, sB>>>(col);
    k_scan_local<<<nb, 1024, 0, sB>>>();      // produces g_dinv
    cudaEventRecord(evDinv, sB);
    k_scan_add<<<nb, 1024, 0, sB>>>();
    k_fill_csr<<<2048, 256, 0, sB>>>(row, col);
    cudaEventRecord(evCsr, sB);

    // stream 0: weight prep; gemmF epilogue needs dinv
    k_setup_w<<<(HID * HID + 255) / 256, 256>>>(conv_W, enc_b, batch);
    k_fuse_w<<<dim3(8, 8), dim3(32, 8)>>>(enc_W, conv_W);
    cudaStreamWaitEvent(0, evDinv, 0);
    k_gemm<true><<<ggrid, 256, SMEM_F>>>(x, g_Wf16_ptr, g_bf_ptr, g_h2q_ptr, N_NODES);

    // join: aggregation needs full CSR
    cudaStreamWaitEvent(0, evCsr, 0);

    k_aggregate<<<(N_NODES + 3) / 4, 256>>>(g_h2q_ptr, conv_b, g_hh_ptr);
    k_gemm<false><<<ggrid, 256, SMEM_H>>>(g_hh_ptr, g_Wt16_ptr, nullptr, g_h2q_ptr, N_NODES);
    k_aggregate<<<(N_NODES + 3) / 4, 256>>>(g_h2q_ptr, conv_b + HID, g_hh_ptr);
    k_pool_cls<<<NGRAPH, 256>>>(g_hh_ptr, out_W, out_b, out);
}